// round 9
// baseline (speedup 1.0000x reference)
#include <cuda_runtime.h>
#include <cuda_fp16.h>
#include <math.h>

#define NN 50000
#define EE 800000
#define DD 64

typedef unsigned long long u64;

// ---------------- scratch (static device globals; no runtime allocation) ----
__device__ __align__(16) float g_esrc[NN*DD];
__device__ __align__(16) float g_edst[NN*DD];
__device__ __align__(16) float g_Bh[NN*DD];
__device__ __align__(16) float g_xs[NN*DD];      // xs, then x_pre in-place
__device__ __align__(16) __half g_mh[EE*DD];     // m stored fp16 (102.4 MB)
__device__ __align__(16) __half g_sumh_h[NN*DD]; // fp16 segment sums
__device__ __align__(16) __half g_sums_h[NN*DD];
// stats: [0..63] e_sum, [64..127] e_sumsq, [128..191] n_sum, [192..255] n_sumsq
__device__ __align__(16) float g_stats[256];
// bn params: [0..63] scale_n, [64..127] shift_n, [128..191] scale_e, [192..255] shift_e
__device__ __align__(16) float g_bn[256];

__device__ __forceinline__ void fma4(float4& acc, float s, const float4& w) {
    acc.x += s * w.x; acc.y += s * w.y; acc.z += s * w.z; acc.w += s * w.w;
}
__device__ __forceinline__ float fsigmoid(float x) { return 1.f / (1.f + __expf(-x)); }
__device__ __forceinline__ float fsilu(float z)    { return z / (1.f + __expf(-z)); }

// packed dual-lane fp32 fma (sm_100+; ptxas never emits this from C++)
__device__ __forceinline__ void ffma2(u64& acc, u64 a, u64 b) {
    asm("fma.rn.f32x2 %0, %1, %2, %0;" : "+l"(acc) : "l"(a), "l"(b));
}
__device__ __forceinline__ u64 pack2(float x, float y) {
    float2 t = make_float2(x, y); return *(u64*)&t;
}
__device__ __forceinline__ float2 unpack2(u64 v) { return *(float2*)&v; }

__device__ __forceinline__ unsigned h2bits(__half2 h) { return *(unsigned*)&h; }

// 8-half vectorized no-return fp16 reduction: 1 instruction, 16 bytes
__device__ __forceinline__ void red_add_v4_h2(__half* addr,
                                              __half2 a, __half2 b,
                                              __half2 c, __half2 d) {
    asm volatile("red.global.add.noftz.v4.f16x2 [%0], {%1,%2,%3,%4};"
                 :: "l"(addr), "r"(h2bits(a)), "r"(h2bits(b)),
                    "r"(h2bits(c)), "r"(h2bits(d)) : "memory");
}

// ---------------- K0a / K0b: zero accumulators (keeps k_edge at launch 3) ---
__global__ void __launch_bounds__(256) k_zero_a() {
    int stride = gridDim.x * blockDim.x;
    unsigned* p = (unsigned*)g_sumh_h;             // NN*DD/2 uints
    for (int i = blockIdx.x * blockDim.x + threadIdx.x; i < NN*DD/2; i += stride)
        p[i] = 0u;
    int t = blockIdx.x * blockDim.x + threadIdx.x;
    if (t < 256) g_stats[t] = 0.f;
}
__global__ void __launch_bounds__(256) k_zero_b() {
    int stride = gridDim.x * blockDim.x;
    unsigned* p = (unsigned*)g_sums_h;
    for (int i = blockIdx.x * blockDim.x + threadIdx.x; i < NN*DD/2; i += stride)
        p[i] = 0u;
}

// ---------------- K1: node GEMMs (e_src, e_dst, Bh, xs), f32x2 --------------
__global__ void __launch_bounds__(256, 2) k_node_gemm(
    const float* __restrict__ nf,
    const float* __restrict__ Wsg, const float* __restrict__ bsg,
    const float* __restrict__ Wdg, const float* __restrict__ bdg,
    const float* __restrict__ Wdu, const float* __restrict__ bdu,
    const float* __restrict__ Wsu, const float* __restrict__ bsu)
{
    extern __shared__ float sm[];
    float* sW    = sm;            // 16384 floats
    float* srow2 = sm + 16384;    // 8192 floats
    int tid = threadIdx.x;
    int tx = tid & 15, ty = tid >> 4;

    for (int i = tid; i < 4096; i += 256) {
        sW[i]         = Wsg[i];
        sW[4096 + i]  = Wdg[i];
        sW[8192 + i]  = Wdu[i];
        sW[12288 + i] = Wsu[i];
    }
    u64 bias[4][2];
    bias[0][0] = pack2(bsg[tx*4], bsg[tx*4+1]); bias[0][1] = pack2(bsg[tx*4+2], bsg[tx*4+3]);
    bias[1][0] = pack2(bdg[tx*4], bdg[tx*4+1]); bias[1][1] = pack2(bdg[tx*4+2], bdg[tx*4+3]);
    bias[2][0] = pack2(bdu[tx*4], bdu[tx*4+1]); bias[2][1] = pack2(bdu[tx*4+2], bdu[tx*4+3]);
    bias[3][0] = pack2(bsu[tx*4], bsu[tx*4+1]); bias[3][1] = pack2(bsu[tx*4+2], bsu[tx*4+3]);

    int nchunk = (NN + 63) / 64;
    for (int c = blockIdx.x; c < nchunk; c += gridDim.x) {
        int base = c * 64;
        __syncthreads();
        #pragma unroll
        for (int l = 0; l < 4; l++) {
            int idx = tid + l * 256;              // float4 index 0..1023
            int r = idx >> 4, c4 = (idx & 15) * 4;
            int row = base + r;
            float4 v = make_float4(0.f, 0.f, 0.f, 0.f);
            if (row < NN) v = *(const float4*)(nf + row*64 + c4);
            float* d = srow2 + r*128 + c4*2;
            ((float4*)d)[0] = make_float4(v.x, v.x, v.y, v.y);
            ((float4*)d)[1] = make_float4(v.z, v.z, v.w, v.w);
        }
        __syncthreads();

        u64 acc[4][4][2];
        #pragma unroll
        for (int j = 0; j < 4; j++)
            #pragma unroll
            for (int r = 0; r < 4; r++) { acc[j][r][0] = bias[j][0]; acc[j][r][1] = bias[j][1]; }

        const float* wp = sW + tx*4;
        #pragma unroll 4
        for (int k = 0; k < 64; k += 2) {
            ulonglong2 A[4];
            #pragma unroll
            for (int r = 0; r < 4; r++)
                A[r] = *(const ulonglong2*)(srow2 + (ty*4+r)*128 + k*2);
            #pragma unroll
            for (int j = 0; j < 4; j++) {
                ulonglong2 W0 = *(const ulonglong2*)(wp + j*4096 + k*64);
                ulonglong2 W1 = *(const ulonglong2*)(wp + j*4096 + (k+1)*64);
                #pragma unroll
                for (int r = 0; r < 4; r++) {
                    ffma2(acc[j][r][0], A[r].x, W0.x);
                    ffma2(acc[j][r][1], A[r].x, W0.y);
                    ffma2(acc[j][r][0], A[r].y, W1.x);
                    ffma2(acc[j][r][1], A[r].y, W1.y);
                }
            }
        }
        #pragma unroll
        for (int r = 0; r < 4; r++) {
            int row = base + ty*4 + r;
            if (row < NN) {
                int off = row*64 + tx*4;
                float2 a0, a1;
                a0 = unpack2(acc[0][r][0]); a1 = unpack2(acc[0][r][1]);
                *(float4*)&g_esrc[off] = make_float4(a0.x, a0.y, a1.x, a1.y);
                a0 = unpack2(acc[1][r][0]); a1 = unpack2(acc[1][r][1]);
                *(float4*)&g_edst[off] = make_float4(a0.x, a0.y, a1.x, a1.y);
                a0 = unpack2(acc[2][r][0]); a1 = unpack2(acc[2][r][1]);
                *(float4*)&g_Bh[off]   = make_float4(a0.x, a0.y, a1.x, a1.y);
                a0 = unpack2(acc[3][r][0]); a1 = unpack2(acc[3][r][1]);
                *(float4*)&g_xs[off]   = make_float4(a0.x, a0.y, a1.x, a1.y);
            }
        }
    }
}

// ---------------- K2: edge kernel -------------------------------------------
// 64 edges/chunk; thread map: tx = tid&7 -> features tx*8..tx*8+7 (8 consecutive),
// ty = tid>>3 -> 2 edges (ty*2, ty*2+1). One red.v4.f16x2 per (edge,array):
// 16 REDG lanes/edge instead of 32.
// dyn smem: sW 4096 | srow 4096 | sidx 128 | sred 256 = 8576 floats (~33.5 KB)
__global__ void __launch_bounds__(256, 3) k_edge(
    const float* __restrict__ ef, const int* __restrict__ src, const int* __restrict__ dst,
    const float* __restrict__ Weg, const float* __restrict__ beg)
{
    extern __shared__ float sm[];
    float* sW   = sm;                     // 4096 floats
    float* srow = sm + 4096;              // 4096 floats (64 rows x 64)
    int*   sidx = (int*)(sm + 8192);      // 128 ints: src[64], dst[64]
    float* sred = sm + 8320;              // 256 floats

    int tid = threadIdx.x;
    int tx = tid & 7, ty = tid >> 3;
    for (int i = tid; i < 4096; i += 256) sW[i] = Weg[i];
    float4 bbA = *(const float4*)(beg + tx*8);
    float4 bbB = *(const float4*)(beg + tx*8 + 4);

    float ls[8] = {0.f,0.f,0.f,0.f,0.f,0.f,0.f,0.f};
    float lq[8] = {0.f,0.f,0.f,0.f,0.f,0.f,0.f,0.f};

    int nchunk = EE / 64;                 // 12500
    for (int c = blockIdx.x; c < nchunk; c += gridDim.x) {
        int base = c * 64;
        __syncthreads();
        #pragma unroll
        for (int l = 0; l < 4; l++) {
            int idx = tid + l * 256;             // float4 index 0..1023
            int r = idx >> 4, c4 = (idx & 15) * 4;
            *(float4*)(srow + r*64 + c4) = *(const float4*)(ef + (base + r)*64 + c4);
        }
        if (tid < 64)       sidx[tid] = src[base + tid];
        else if (tid < 128) sidx[tid] = dst[base + tid - 64];
        __syncthreads();

        float4 accA[2], accB[2];
        accA[0] = bbA; accA[1] = bbA; accB[0] = bbB; accB[1] = bbB;

        const float* wp  = sW + tx*8;
        const float* ap0 = srow + (ty*2)*64;
        const float* ap1 = srow + (ty*2+1)*64;
        #pragma unroll 8
        for (int k = 0; k < 64; k += 2) {
            float4 w0a = *(const float4*)(wp + k*64);
            float4 w0b = *(const float4*)(wp + k*64 + 4);
            float4 w1a = *(const float4*)(wp + (k+1)*64);
            float4 w1b = *(const float4*)(wp + (k+1)*64 + 4);
            float2 a0 = *(const float2*)(ap0 + k);
            float2 a1 = *(const float2*)(ap1 + k);
            fma4(accA[0], a0.x, w0a); fma4(accB[0], a0.x, w0b);
            fma4(accA[0], a0.y, w1a); fma4(accB[0], a0.y, w1b);
            fma4(accA[1], a1.x, w0a); fma4(accB[1], a1.x, w0b);
            fma4(accA[1], a1.y, w1a); fma4(accB[1], a1.y, w1b);
        }

        #pragma unroll
        for (int r = 0; r < 2; r++) {
            int row = ty*2 + r;
            int e = base + row;
            int s = sidx[row], t = sidx[64 + row];
            const int soff = s*64 + tx*8;
            const int toff = t*64 + tx*8;
            float4 es0 = *(const float4*)&g_esrc[soff];
            float4 es1 = *(const float4*)&g_esrc[soff+4];
            float4 ed0 = *(const float4*)&g_edst[toff];
            float4 ed1 = *(const float4*)&g_edst[toff+4];
            float4 m0, m1;
            m0.x = accA[r].x + es0.x + ed0.x;
            m0.y = accA[r].y + es0.y + ed0.y;
            m0.z = accA[r].z + es0.z + ed0.z;
            m0.w = accA[r].w + es0.w + ed0.w;
            m1.x = accB[r].x + es1.x + ed1.x;
            m1.y = accB[r].y + es1.y + ed1.y;
            m1.z = accB[r].z + es1.z + ed1.z;
            m1.w = accB[r].w + es1.w + ed1.w;

            __half2 hm0 = __floats2half2_rn(m0.x, m0.y);
            __half2 hm1 = __floats2half2_rn(m0.z, m0.w);
            __half2 hm2 = __floats2half2_rn(m1.x, m1.y);
            __half2 hm3 = __floats2half2_rn(m1.z, m1.w);
            *(uint4*)(g_mh + e*64 + tx*8) =
                make_uint4(h2bits(hm0), h2bits(hm1), h2bits(hm2), h2bits(hm3));

            ls[0] += m0.x; lq[0] += m0.x*m0.x;
            ls[1] += m0.y; lq[1] += m0.y*m0.y;
            ls[2] += m0.z; lq[2] += m0.z*m0.z;
            ls[3] += m0.w; lq[3] += m0.w*m0.w;
            ls[4] += m1.x; lq[4] += m1.x*m1.x;
            ls[5] += m1.y; lq[5] += m1.y*m1.y;
            ls[6] += m1.z; lq[6] += m1.z*m1.z;
            ls[7] += m1.w; lq[7] += m1.w*m1.w;

            float sg0 = fsigmoid(m0.x), sg1 = fsigmoid(m0.y);
            float sg2 = fsigmoid(m0.z), sg3 = fsigmoid(m0.w);
            float sg4 = fsigmoid(m1.x), sg5 = fsigmoid(m1.y);
            float sg6 = fsigmoid(m1.z), sg7 = fsigmoid(m1.w);

            red_add_v4_h2(g_sums_h + toff,
                          __floats2half2_rn(sg0, sg1), __floats2half2_rn(sg2, sg3),
                          __floats2half2_rn(sg4, sg5), __floats2half2_rn(sg6, sg7));

            float4 bh0 = *(const float4*)&g_Bh[soff];
            float4 bh1 = *(const float4*)&g_Bh[soff+4];
            red_add_v4_h2(g_sumh_h + toff,
                          __floats2half2_rn(bh0.x*sg0, bh0.y*sg1),
                          __floats2half2_rn(bh0.z*sg2, bh0.w*sg3),
                          __floats2half2_rn(bh1.x*sg4, bh1.y*sg5),
                          __floats2half2_rn(bh1.z*sg6, bh1.w*sg7));
        }
    }

    // block-level BN stats reduction: feature d = tx*8 + comp, reduce over ty
    #pragma unroll
    for (int comp = 0; comp < 8; comp++) {
        __syncthreads();
        sred[tid] = ls[comp];
        __syncthreads();
        if (ty == 0) {          // tids 0..7, tx = tid
            float ssum = 0.f;
            #pragma unroll
            for (int j = 0; j < 32; j++) ssum += sred[j*8 + tx];
            atomicAdd(&g_stats[tx*8 + comp], ssum);
        }
        __syncthreads();
        sred[tid] = lq[comp];
        __syncthreads();
        if (ty == 0) {
            float ssum = 0.f;
            #pragma unroll
            for (int j = 0; j < 32; j++) ssum += sred[j*8 + tx];
            atomicAdd(&g_stats[64 + tx*8 + comp], ssum);
        }
    }
}

// ---------------- K3: node finalize: x_pre = xs + h, node-BN stats -----------
__global__ void __launch_bounds__(256) k_node_fin() {
    int tid = threadIdx.x;
    int stride = gridDim.x * 256;    // multiple of 32 -> dpair invariant per thread
    float ls0 = 0.f, ls1 = 0.f, lq0 = 0.f, lq1 = 0.f;
    const __half2* ph = (const __half2*)g_sumh_h;
    const __half2* ps = (const __half2*)g_sums_h;
    for (int j = blockIdx.x * 256 + tid; j < NN*DD/2; j += stride) {
        float2 fh = __half22float2(ph[j]);
        float2 fs = __half22float2(ps[j]);
        float2 xs = *(float2*)&g_xs[j*2];
        float xp0 = xs.x + fh.x / (fs.x + 1e-6f);
        float xp1 = xs.y + fh.y / (fs.y + 1e-6f);
        *(float2*)&g_xs[j*2] = make_float2(xp0, xp1);
        ls0 += xp0; lq0 += xp0*xp0;
        ls1 += xp1; lq1 += xp1*xp1;
    }
    __shared__ float sred[256];
    int l = tid & 31;                 // dpair index; d0 = l*2
    sred[tid] = ls0;
    __syncthreads();
    if (tid < 32) {
        float s = 0.f;
        #pragma unroll
        for (int g = 0; g < 8; g++) s += sred[g*32 + tid];
        atomicAdd(&g_stats[128 + tid*2], s);
    }
    __syncthreads();
    sred[tid] = ls1;
    __syncthreads();
    if (tid < 32) {
        float s = 0.f;
        #pragma unroll
        for (int g = 0; g < 8; g++) s += sred[g*32 + tid];
        atomicAdd(&g_stats[128 + tid*2 + 1], s);
    }
    __syncthreads();
    sred[tid] = lq0;
    __syncthreads();
    if (tid < 32) {
        float s = 0.f;
        #pragma unroll
        for (int g = 0; g < 8; g++) s += sred[g*32 + tid];
        atomicAdd(&g_stats[192 + tid*2], s);
    }
    __syncthreads();
    sred[tid] = lq1;
    __syncthreads();
    if (tid < 32) {
        float s = 0.f;
        #pragma unroll
        for (int g = 0; g < 8; g++) s += sred[g*32 + tid];
        atomicAdd(&g_stats[192 + tid*2 + 1], s);
    }
    (void)l;
}

// ---------------- K4: BN scale/shift ----------------------------------------
__global__ void k_bn(const float* __restrict__ gn, const float* __restrict__ btn,
                     const float* __restrict__ ge, const float* __restrict__ bte)
{
    int d = threadIdx.x;   // 64 threads
    float me = g_stats[d] * (1.f / EE);
    float ve = g_stats[64 + d] * (1.f / EE) - me * me;
    float se = ge[d] * rsqrtf(ve + 1e-5f);
    g_bn[128 + d] = se;
    g_bn[192 + d] = bte[d] - me * se;

    float mn = g_stats[128 + d] * (1.f / NN);
    float vn = g_stats[192 + d] * (1.f / NN) - mn * mn;
    float sn = gn[d] * rsqrtf(vn + 1e-5f);
    g_bn[d]      = sn;
    g_bn[64 + d] = btn[d] - mn * sn;
}

// ---------------- K5: node output -------------------------------------------
__global__ void __launch_bounds__(256) k_node_out(const float* __restrict__ nf,
                                                  float* __restrict__ out)
{
    int i4 = blockIdx.x * 256 + threadIdx.x;       // float4 index
    if (i4 >= NN*DD/4) return;
    int d4 = (i4 & 15) * 4;
    float4 sc = *(const float4*)&g_bn[d4];
    float4 sh = *(const float4*)&g_bn[64 + d4];
    float4 xp = *(const float4*)&g_xs[i4*4];
    float4 bs = *(const float4*)&nf[i4*4];
    float4 o;
    o.x = bs.x + fsilu(xp.x*sc.x + sh.x);
    o.y = bs.y + fsilu(xp.y*sc.y + sh.y);
    o.z = bs.z + fsilu(xp.z*sc.z + sh.z);
    o.w = bs.w + fsilu(xp.w*sc.w + sh.w);
    *(float4*)&out[i4*4] = o;
}

// ---------------- K6: edge output (fp16 m) -----------------------------------
__global__ void __launch_bounds__(256) k_edge_out(const float* __restrict__ ef,
                                                  float* __restrict__ out)
{
    int stride = gridDim.x * 256;
    for (int i4 = blockIdx.x * 256 + threadIdx.x; i4 < EE*DD/4; i4 += stride) {
        int d4 = (i4 & 15) * 4;
        float4 sc = *(const float4*)&g_bn[128 + d4];
        float4 sh = *(const float4*)&g_bn[192 + d4];
        uint2 pk = *(const uint2*)(g_mh + i4*4);
        __half2 h0 = *(__half2*)&pk.x;
        __half2 h1 = *(__half2*)&pk.y;
        float2 m01 = __half22float2(h0);
        float2 m23 = __half22float2(h1);
        float4 bs = *(const float4*)&ef[i4*4];
        float4 o;
        o.x = bs.x + fsilu(m01.x*sc.x + sh.x);
        o.y = bs.y + fsilu(m01.y*sc.y + sh.y);
        o.z = bs.z + fsilu(m23.x*sc.z + sh.z);
        o.w = bs.w + fsilu(m23.y*sc.w + sh.w);
        *(float4*)&out[i4*4] = o;
    }
}

// ---------------- launcher ---------------------------------------------------
extern "C" void kernel_launch(void* const* d_in, const int* in_sizes, int n_in,
                              void* d_out, int out_size)
{
    const float* nf  = (const float*)d_in[0];
    const float* ef  = (const float*)d_in[1];
    const int*   src = (const int*)  d_in[2];
    const int*   dst = (const int*)  d_in[3];
    const float *Wsg = (const float*)d_in[4],  *bsg = (const float*)d_in[5];
    const float *Wdg = (const float*)d_in[6],  *bdg = (const float*)d_in[7];
    const float *Weg = (const float*)d_in[8],  *beg = (const float*)d_in[9];
    const float *Wsu = (const float*)d_in[10], *bsu = (const float*)d_in[11];
    const float *Wdu = (const float*)d_in[12], *bdu = (const float*)d_in[13];
    const float *gn  = (const float*)d_in[14], *btn = (const float*)d_in[15];
    const float *ge  = (const float*)d_in[16], *bte = (const float*)d_in[17];
    float* out = (float*)d_out;

    static const size_t k1_smem = (16384 + 8192) * sizeof(float);   // 96 KB
    static const size_t k2_smem = 8576 * sizeof(float);             // ~33.5 KB
    cudaFuncSetAttribute(k_node_gemm, cudaFuncAttributeMaxDynamicSharedMemorySize,
                         (int)k1_smem);
    cudaFuncSetAttribute(k_edge, cudaFuncAttributeMaxDynamicSharedMemorySize,
                         (int)k2_smem);

    k_zero_a<<<1024, 256>>>();                                        // launch 0
    k_node_gemm<<<592, 256, k1_smem>>>(nf, Wsg, bsg, Wdg, bdg,
                                       Wdu, bdu, Wsu, bsu);           // launch 1
    k_zero_b<<<1024, 256>>>();                                        // launch 2
    k_edge<<<2960, 256, k2_smem>>>(ef, src, dst, Weg, beg);           // launch 3 (profiled)
    k_node_fin<<<1024, 256>>>();
    k_bn<<<1, 64>>>(gn, btn, ge, bte);
    k_node_out<<<3125, 256>>>(nf, out);
    k_edge_out<<<8192, 256>>>(ef, out + NN*DD);
}

// round 11
// speedup vs baseline: 1.6078x; 1.6078x over previous
#include <cuda_runtime.h>
#include <cuda_fp16.h>
#include <math.h>
#include <cstdint>

#define NN 50000
#define EE 800000
#define DD 64

typedef unsigned long long u64;

// ---------------- scratch (static device globals; no runtime allocation) ----
__device__ __align__(16) float g_esrc[NN*DD];
__device__ __align__(16) float g_edst[NN*DD];
__device__ __align__(16) float g_Bh[NN*DD];
__device__ __align__(16) float g_xs[NN*DD];      // xs, then x_pre in-place
__device__ __align__(16) __half g_mh[EE*DD];     // m stored fp16 (102.4 MB)
__device__ __align__(16) float g_sumh[NN*DD];
__device__ __align__(16) float g_sums[NN*DD];
// stats: [0..63] e_sum, [64..127] e_sumsq, [128..191] n_sum, [192..255] n_sumsq
__device__ __align__(16) float g_stats[256];
// bn params: [0..63] scale_n, [64..127] shift_n, [128..191] scale_e, [192..255] shift_e
__device__ __align__(16) float g_bn[256];

__device__ __forceinline__ float fsigmoid(float x) { return 1.f / (1.f + __expf(-x)); }
__device__ __forceinline__ float fsilu(float z)    { return z / (1.f + __expf(-z)); }
__device__ __forceinline__ unsigned h2bits(__half2 h) { return *(unsigned*)&h; }

// packed dual-lane fp32 fma (node GEMM)
__device__ __forceinline__ void ffma2(u64& acc, u64 a, u64 b) {
    asm("fma.rn.f32x2 %0, %1, %2, %0;" : "+l"(acc) : "l"(a), "l"(b));
}
__device__ __forceinline__ u64 pack2(float x, float y) {
    float2 t = make_float2(x, y); return *(u64*)&t;
}
__device__ __forceinline__ float2 unpack2(u64 v) { return *(float2*)&v; }

// vectorized no-return fp32 reduction: 1 instruction, 16 bytes, 4 lanes
__device__ __forceinline__ void red_add_v4(float* addr, float a, float b, float c, float d) {
    asm volatile("red.global.add.v4.f32 [%0], {%1,%2,%3,%4};"
                 :: "l"(addr), "f"(a), "f"(b), "f"(c), "f"(d) : "memory");
}

// warp-level tensor-core mma (baseline PTX, valid on sm_103 non-'a' target)
__device__ __forceinline__ void mma_16816(float* c, uint32_t a0, uint32_t a1,
                                          uint32_t a2, uint32_t a3,
                                          uint32_t b0, uint32_t b1) {
    asm volatile(
        "mma.sync.aligned.m16n8k16.row.col.f32.f16.f16.f32 "
        "{%0,%1,%2,%3}, {%4,%5,%6,%7}, {%8,%9}, {%0,%1,%2,%3};"
        : "+f"(c[0]), "+f"(c[1]), "+f"(c[2]), "+f"(c[3])
        : "r"(a0), "r"(a1), "r"(a2), "r"(a3), "r"(b0), "r"(b1));
}

// k_edge smem byte offsets (dynamic smem, 64512 B total)
#define SM_IDX  0         // 256 ints (1024 B)
#define SM_SRED 1024      // 256 floats (1024 B)
#define SM_W    2048      // 64 rows x 72 halves packed  (9216 B)
#define SM_A    11264     // 128 rows x 72 halves        (18432 B)
#define SM_D    29696     // 128 rows x 68 floats        (34816 B)
#define SM_EDGE_TOTAL 64512

// ---------------- K0a / K0b: zero accumulators (keeps k_edge at launch 3) ---
__global__ void __launch_bounds__(256) k_zero_a() {
    int stride = gridDim.x * blockDim.x;
    for (int i = blockIdx.x * blockDim.x + threadIdx.x; i < NN*DD; i += stride)
        g_sumh[i] = 0.f;
    int t = blockIdx.x * blockDim.x + threadIdx.x;
    if (t < 256) g_stats[t] = 0.f;
}
__global__ void __launch_bounds__(256) k_zero_b() {
    int stride = gridDim.x * blockDim.x;
    for (int i = blockIdx.x * blockDim.x + threadIdx.x; i < NN*DD; i += stride)
        g_sums[i] = 0.f;
}

// ---------------- K1: node GEMMs (e_src, e_dst, Bh, xs), f32x2 --------------
__global__ void __launch_bounds__(256, 2) k_node_gemm(
    const float* __restrict__ nf,
    const float* __restrict__ Wsg, const float* __restrict__ bsg,
    const float* __restrict__ Wdg, const float* __restrict__ bdg,
    const float* __restrict__ Wdu, const float* __restrict__ bdu,
    const float* __restrict__ Wsu, const float* __restrict__ bsu)
{
    extern __shared__ float sm[];
    float* sW    = sm;            // 16384 floats
    float* srow2 = sm + 16384;    // 8192 floats
    int tid = threadIdx.x;
    int tx = tid & 15, ty = tid >> 4;

    for (int i = tid; i < 4096; i += 256) {
        sW[i]         = Wsg[i];
        sW[4096 + i]  = Wdg[i];
        sW[8192 + i]  = Wdu[i];
        sW[12288 + i] = Wsu[i];
    }
    u64 bias[4][2];
    bias[0][0] = pack2(bsg[tx*4], bsg[tx*4+1]); bias[0][1] = pack2(bsg[tx*4+2], bsg[tx*4+3]);
    bias[1][0] = pack2(bdg[tx*4], bdg[tx*4+1]); bias[1][1] = pack2(bdg[tx*4+2], bdg[tx*4+3]);
    bias[2][0] = pack2(bdu[tx*4], bdu[tx*4+1]); bias[2][1] = pack2(bdu[tx*4+2], bdu[tx*4+3]);
    bias[3][0] = pack2(bsu[tx*4], bsu[tx*4+1]); bias[3][1] = pack2(bsu[tx*4+2], bsu[tx*4+3]);

    int nchunk = (NN + 63) / 64;
    for (int c = blockIdx.x; c < nchunk; c += gridDim.x) {
        int base = c * 64;
        __syncthreads();
        #pragma unroll
        for (int l = 0; l < 4; l++) {
            int idx = tid + l * 256;
            int r = idx >> 4, c4 = (idx & 15) * 4;
            int row = base + r;
            float4 v = make_float4(0.f, 0.f, 0.f, 0.f);
            if (row < NN) v = *(const float4*)(nf + row*64 + c4);
            float* d = srow2 + r*128 + c4*2;
            ((float4*)d)[0] = make_float4(v.x, v.x, v.y, v.y);
            ((float4*)d)[1] = make_float4(v.z, v.z, v.w, v.w);
        }
        __syncthreads();

        u64 acc[4][4][2];
        #pragma unroll
        for (int j = 0; j < 4; j++)
            #pragma unroll
            for (int r = 0; r < 4; r++) { acc[j][r][0] = bias[j][0]; acc[j][r][1] = bias[j][1]; }

        const float* wp = sW + tx*4;
        #pragma unroll 4
        for (int k = 0; k < 64; k += 2) {
            ulonglong2 A[4];
            #pragma unroll
            for (int r = 0; r < 4; r++)
                A[r] = *(const ulonglong2*)(srow2 + (ty*4+r)*128 + k*2);
            #pragma unroll
            for (int j = 0; j < 4; j++) {
                ulonglong2 W0 = *(const ulonglong2*)(wp + j*4096 + k*64);
                ulonglong2 W1 = *(const ulonglong2*)(wp + j*4096 + (k+1)*64);
                #pragma unroll
                for (int r = 0; r < 4; r++) {
                    ffma2(acc[j][r][0], A[r].x, W0.x);
                    ffma2(acc[j][r][1], A[r].x, W0.y);
                    ffma2(acc[j][r][0], A[r].y, W1.x);
                    ffma2(acc[j][r][1], A[r].y, W1.y);
                }
            }
        }
        #pragma unroll
        for (int r = 0; r < 4; r++) {
            int row = base + ty*4 + r;
            if (row < NN) {
                int off = row*64 + tx*4;
                float2 a0, a1;
                a0 = unpack2(acc[0][r][0]); a1 = unpack2(acc[0][r][1]);
                *(float4*)&g_esrc[off] = make_float4(a0.x, a0.y, a1.x, a1.y);
                a0 = unpack2(acc[1][r][0]); a1 = unpack2(acc[1][r][1]);
                *(float4*)&g_edst[off] = make_float4(a0.x, a0.y, a1.x, a1.y);
                a0 = unpack2(acc[2][r][0]); a1 = unpack2(acc[2][r][1]);
                *(float4*)&g_Bh[off]   = make_float4(a0.x, a0.y, a1.x, a1.y);
                a0 = unpack2(acc[3][r][0]); a1 = unpack2(acc[3][r][1]);
                *(float4*)&g_xs[off]   = make_float4(a0.x, a0.y, a1.x, a1.y);
            }
        }
    }
}

// ---------------- K2: edge kernel — mma.sync f16 GEMM + fused epilogue ------
// 128 edges/chunk. Warp w computes rows w*16..w*16+15 (4 k-steps x 8 n-tiles
// of m16n8k16). A fp16 in smem (rows padded to 72 halves, conflict-free frag
// loads); B = Weg^T fp16 packed so one LDS.64 yields a full B fragment. D
// staged to smem (rows padded to 68 floats), consumed by the R7 epilogue.
__global__ void __launch_bounds__(256, 2) k_edge(
    const float* __restrict__ ef, const int* __restrict__ src, const int* __restrict__ dst,
    const float* __restrict__ Weg, const float* __restrict__ beg)
{
    extern __shared__ char smem[];
    int*    sidx = (int*)(smem + SM_IDX);
    float*  sred = (float*)(smem + SM_SRED);
    __half* sW   = (__half*)(smem + SM_W);
    __half* sA   = (__half*)(smem + SM_A);
    float*  sD   = (float*)(smem + SM_D);

    int tid = threadIdx.x;
    int wid = tid >> 5, lane = tid & 31;
    int tig = lane & 3, grp = lane >> 2;
    int tx = tid & 15, ty = tid >> 4;

    // W fill: packed so B frag (b0,b1) = one 8-byte load.
    // For k-step s, quad q: bytes at n*144 + s*32 + q*8 hold
    // {W[s*16+2q][n], W[s*16+2q+1][n], W[s*16+2q+8][n], W[s*16+2q+9][n]}
    for (int i = tid; i < 4096; i += 256) {
        int k = i >> 6, n = i & 63;
        int s = k >> 4, r = k & 15;
        int q = (r & 7) >> 1, hi = r >> 3, lo = r & 1;
        sW[n*72 + s*16 + q*4 + hi*2 + lo] = __float2half_rn(Weg[i]);
    }
    float4 bb = *(const float4*)(beg + tx*4);

    float ls[4] = {0.f,0.f,0.f,0.f};
    float lq[4] = {0.f,0.f,0.f,0.f};

    int nchunk = EE / 128;    // 6250
    for (int c = blockIdx.x; c < nchunk; c += gridDim.x) {
        int base = c * 128;
        __syncthreads();      // prev epilogue done (sA/sidx reuse)
        #pragma unroll
        for (int l = 0; l < 8; l++) {
            int idx = tid + l * 256;             // float4 index 0..2047
            int r = idx >> 4, c4 = (idx & 15) * 4;
            float4 v = *(const float4*)(ef + (base + r)*64 + c4);
            __half2 h0 = __floats2half2_rn(v.x, v.y);
            __half2 h1 = __floats2half2_rn(v.z, v.w);
            *(uint2*)(sA + r*72 + c4) = make_uint2(h2bits(h0), h2bits(h1));
        }
        if (tid < 128) sidx[tid] = src[base + tid];
        else           sidx[tid] = dst[base + tid - 128];
        __syncthreads();

        float acc[8][4];
        #pragma unroll
        for (int j = 0; j < 8; j++) {
            acc[j][0] = 0.f; acc[j][1] = 0.f; acc[j][2] = 0.f; acc[j][3] = 0.f;
        }

        const __half* arow = sA + (wid*16 + grp)*72;
        #pragma unroll
        for (int s = 0; s < 4; s++) {
            int k0 = s*16 + tig*2;
            uint32_t a0 = *(const uint32_t*)(arow + k0);
            uint32_t a1 = *(const uint32_t*)(arow + 8*72 + k0);
            uint32_t a2 = *(const uint32_t*)(arow + k0 + 8);
            uint32_t a3 = *(const uint32_t*)(arow + 8*72 + k0 + 8);
            #pragma unroll
            for (int j = 0; j < 8; j++) {
                uint2 b = *(const uint2*)(sW + (j*8 + grp)*72 + s*16 + tig*4);
                mma_16816(acc[j], a0, a1, a2, a3, b.x, b.y);
            }
        }

        // stage D to smem
        float* drow = sD + (wid*16 + grp)*68;
        #pragma unroll
        for (int j = 0; j < 8; j++) {
            *(float2*)(drow + j*8 + tig*2)        = make_float2(acc[j][0], acc[j][1]);
            *(float2*)(drow + 8*68 + j*8 + tig*2) = make_float2(acc[j][2], acc[j][3]);
        }
        __syncthreads();

        // epilogue (R7 mapping: ty -> 8 rows, tx -> col quad)
        #pragma unroll
        for (int r = 0; r < 8; r++) {
            int row = ty*8 + r;
            int e = base + row;
            int s = sidx[row], t = sidx[128 + row];
            const int soff = s*64 + tx*4;
            const int toff = t*64 + tx*4;
            float4 dv = *(const float4*)(sD + row*68 + tx*4);
            float4 es = *(const float4*)&g_esrc[soff];
            float4 ed = *(const float4*)&g_edst[toff];
            float4 m;
            m.x = dv.x + bb.x + es.x + ed.x;
            m.y = dv.y + bb.y + es.y + ed.y;
            m.z = dv.z + bb.z + es.z + ed.z;
            m.w = dv.w + bb.w + es.w + ed.w;

            __half2 h0 = __floats2half2_rn(m.x, m.y);
            __half2 h1 = __floats2half2_rn(m.z, m.w);
            *(uint2*)(g_mh + (size_t)e*64 + tx*4) = make_uint2(h2bits(h0), h2bits(h1));

            ls[0] += m.x; lq[0] += m.x*m.x;
            ls[1] += m.y; lq[1] += m.y*m.y;
            ls[2] += m.z; lq[2] += m.z*m.z;
            ls[3] += m.w; lq[3] += m.w*m.w;

            float4 bh = *(const float4*)&g_Bh[soff];
            float sg0 = fsigmoid(m.x), sg1 = fsigmoid(m.y);
            float sg2 = fsigmoid(m.z), sg3 = fsigmoid(m.w);
            red_add_v4(&g_sums[toff], sg0, sg1, sg2, sg3);
            red_add_v4(&g_sumh[toff], bh.x*sg0, bh.y*sg1, bh.z*sg2, bh.w*sg3);
        }
    }

    // block-level BN stats reduction: feature d = tx*4 + comp, reduce over ty
    #pragma unroll
    for (int comp = 0; comp < 4; comp++) {
        __syncthreads();
        sred[tid] = ls[comp];
        __syncthreads();
        if (ty == 0) {
            float ssum = 0.f;
            #pragma unroll
            for (int j = 0; j < 16; j++) ssum += sred[j*16 + tx];
            atomicAdd(&g_stats[tx*4 + comp], ssum);
        }
        __syncthreads();
        sred[tid] = lq[comp];
        __syncthreads();
        if (ty == 0) {
            float ssum = 0.f;
            #pragma unroll
            for (int j = 0; j < 16; j++) ssum += sred[j*16 + tx];
            atomicAdd(&g_stats[64 + tx*4 + comp], ssum);
        }
    }
}

// ---------------- K3: node finalize: x_pre = xs + h, node-BN stats -----------
__global__ void __launch_bounds__(256) k_node_fin() {
    int tid = threadIdx.x;
    int d = tid & 63;
    int stride = gridDim.x * 256;
    float lsum = 0.f, lsq = 0.f;
    for (int i = blockIdx.x * 256 + tid; i < NN*DD; i += stride) {
        float xp = g_xs[i] + g_sumh[i] / (g_sums[i] + 1e-6f);
        g_xs[i] = xp;
        lsum += xp; lsq += xp*xp;
    }
    __shared__ float sred[256];
    sred[tid] = lsum;
    __syncthreads();
    if (tid < 64)
        atomicAdd(&g_stats[128 + d], sred[d] + sred[64+d] + sred[128+d] + sred[192+d]);
    __syncthreads();
    sred[tid] = lsq;
    __syncthreads();
    if (tid < 64)
        atomicAdd(&g_stats[192 + d], sred[d] + sred[64+d] + sred[128+d] + sred[192+d]);
}

// ---------------- K4: BN scale/shift ----------------------------------------
__global__ void k_bn(const float* __restrict__ gn, const float* __restrict__ btn,
                     const float* __restrict__ ge, const float* __restrict__ bte)
{
    int d = threadIdx.x;   // 64 threads
    float me = g_stats[d] * (1.f / EE);
    float ve = g_stats[64 + d] * (1.f / EE) - me * me;
    float se = ge[d] * rsqrtf(ve + 1e-5f);
    g_bn[128 + d] = se;
    g_bn[192 + d] = bte[d] - me * se;

    float mn = g_stats[128 + d] * (1.f / NN);
    float vn = g_stats[192 + d] * (1.f / NN) - mn * mn;
    float sn = gn[d] * rsqrtf(vn + 1e-5f);
    g_bn[d]      = sn;
    g_bn[64 + d] = btn[d] - mn * sn;
}

// ---------------- K5: node output -------------------------------------------
__global__ void __launch_bounds__(256) k_node_out(const float* __restrict__ nf,
                                                  float* __restrict__ out)
{
    int i4 = blockIdx.x * 256 + threadIdx.x;
    if (i4 >= NN*DD/4) return;
    int d4 = (i4 & 15) * 4;
    float4 sc = *(const float4*)&g_bn[d4];
    float4 sh = *(const float4*)&g_bn[64 + d4];
    float4 xp = *(const float4*)&g_xs[i4*4];
    float4 bs = *(const float4*)&nf[i4*4];
    float4 o;
    o.x = bs.x + fsilu(xp.x*sc.x + sh.x);
    o.y = bs.y + fsilu(xp.y*sc.y + sh.y);
    o.z = bs.z + fsilu(xp.z*sc.z + sh.z);
    o.w = bs.w + fsilu(xp.w*sc.w + sh.w);
    *(float4*)&out[i4*4] = o;
}

// ---------------- K6: edge output (fp16 m) -----------------------------------
__global__ void __launch_bounds__(256) k_edge_out(const float* __restrict__ ef,
                                                  float* __restrict__ out)
{
    int stride = gridDim.x * 256;
    for (int i4 = blockIdx.x * 256 + threadIdx.x; i4 < EE*DD/4; i4 += stride) {
        int d4 = (i4 & 15) * 4;
        float4 sc = *(const float4*)&g_bn[128 + d4];
        float4 sh = *(const float4*)&g_bn[192 + d4];
        uint2 pk = *(const uint2*)(g_mh + (size_t)i4*4);
        __half2 h0 = *(__half2*)&pk.x;
        __half2 h1 = *(__half2*)&pk.y;
        float2 m01 = __half22float2(h0);
        float2 m23 = __half22float2(h1);
        float4 bs = *(const float4*)&ef[i4*4];
        float4 o;
        o.x = bs.x + fsilu(m01.x*sc.x + sh.x);
        o.y = bs.y + fsilu(m01.y*sc.y + sh.y);
        o.z = bs.z + fsilu(m23.x*sc.z + sh.z);
        o.w = bs.w + fsilu(m23.y*sc.w + sh.w);
        *(float4*)&out[i4*4] = o;
    }
}

// ---------------- launcher ---------------------------------------------------
extern "C" void kernel_launch(void* const* d_in, const int* in_sizes, int n_in,
                              void* d_out, int out_size)
{
    const float* nf  = (const float*)d_in[0];
    const float* ef  = (const float*)d_in[1];
    const int*   src = (const int*)  d_in[2];
    const int*   dst = (const int*)  d_in[3];
    const float *Wsg = (const float*)d_in[4],  *bsg = (const float*)d_in[5];
    const float *Wdg = (const float*)d_in[6],  *bdg = (const float*)d_in[7];
    const float *Weg = (const float*)d_in[8],  *beg = (const float*)d_in[9];
    const float *Wsu = (const float*)d_in[10], *bsu = (const float*)d_in[11];
    const float *Wdu = (const float*)d_in[12], *bdu = (const float*)d_in[13];
    const float *gn  = (const float*)d_in[14], *btn = (const float*)d_in[15];
    const float *ge  = (const float*)d_in[16], *bte = (const float*)d_in[17];
    float* out = (float*)d_out;

    static const size_t k1_smem = (16384 + 8192) * sizeof(float);   // 96 KB
    cudaFuncSetAttribute(k_node_gemm, cudaFuncAttributeMaxDynamicSharedMemorySize,
                         (int)k1_smem);
    cudaFuncSetAttribute(k_edge, cudaFuncAttributeMaxDynamicSharedMemorySize,
                         SM_EDGE_TOTAL);

    k_zero_a<<<1024, 256>>>();                                        // launch 0
    k_node_gemm<<<592, 256, k1_smem>>>(nf, Wsg, bsg, Wdg, bdg,
                                       Wdu, bdu, Wsu, bsu);           // launch 1
    k_zero_b<<<1024, 256>>>();                                        // launch 2
    k_edge<<<2960, 256, SM_EDGE_TOTAL>>>(ef, src, dst, Weg, beg);     // launch 3 (profiled)
    k_node_fin<<<1024, 256>>>();                                      // launch 4
    k_bn<<<1, 64>>>(gn, btn, ge, bte);                                // launch 5
    k_node_out<<<3125, 256>>>(nf, out);                               // launch 6
    k_edge_out<<<8192, 256>>>(ef, out + NN*DD);                       // launch 7
}

// round 12
// speedup vs baseline: 1.8440x; 1.1469x over previous
#include <cuda_runtime.h>
#include <cuda_fp16.h>
#include <math.h>
#include <cstdint>

#define NN 50000
#define EE 800000
#define DD 64

typedef unsigned long long u64;

// ---------------- scratch (static device globals; no runtime allocation) ----
__device__ __align__(16) float g_esrc[NN*DD];
__device__ __align__(16) float g_edst[NN*DD];
__device__ __align__(16) float g_Bh[NN*DD];
__device__ __align__(16) float g_xs[NN*DD];      // xs, then x_pre in-place
__device__ __align__(16) __half g_mh[EE*DD];     // m stored fp16 (102.4 MB)
__device__ __align__(16) float g_sumh[NN*DD];
__device__ __align__(16) float g_sums[NN*DD];
// stats: [0..63] e_sum, [64..127] e_sumsq, [128..191] n_sum, [192..255] n_sumsq
__device__ __align__(16) float g_stats[256];
// bn params: [0..63] scale_n, [64..127] shift_n, [128..191] scale_e, [192..255] shift_e
__device__ __align__(16) float g_bn[256];

__device__ __forceinline__ float fsigmoid(float x) { return 1.f / (1.f + __expf(-x)); }
__device__ __forceinline__ float fsilu(float z)    { return z / (1.f + __expf(-z)); }
__device__ __forceinline__ unsigned h2bits(__half2 h) { return *(unsigned*)&h; }

// packed dual-lane fp32 fma (node GEMM)
__device__ __forceinline__ void ffma2(u64& acc, u64 a, u64 b) {
    asm("fma.rn.f32x2 %0, %1, %2, %0;" : "+l"(acc) : "l"(a), "l"(b));
}
__device__ __forceinline__ u64 pack2(float x, float y) {
    float2 t = make_float2(x, y); return *(u64*)&t;
}
__device__ __forceinline__ float2 unpack2(u64 v) { return *(float2*)&v; }

// vectorized no-return fp32 reduction: 1 instruction, 16 bytes, 4 lanes
__device__ __forceinline__ void red_add_v4(float* addr, float a, float b, float c, float d) {
    asm volatile("red.global.add.v4.f32 [%0], {%1,%2,%3,%4};"
                 :: "l"(addr), "f"(a), "f"(b), "f"(c), "f"(d) : "memory");
}

// warp-level tensor-core mma (baseline PTX, valid on sm_103 non-'a' target)
__device__ __forceinline__ void mma_16816(float* c, uint32_t a0, uint32_t a1,
                                          uint32_t a2, uint32_t a3,
                                          uint32_t b0, uint32_t b1) {
    asm volatile(
        "mma.sync.aligned.m16n8k16.row.col.f32.f16.f16.f32 "
        "{%0,%1,%2,%3}, {%4,%5,%6,%7}, {%8,%9}, {%0,%1,%2,%3};"
        : "+f"(c[0]), "+f"(c[1]), "+f"(c[2]), "+f"(c[3])
        : "r"(a0), "r"(a1), "r"(a2), "r"(a3), "r"(b0), "r"(b1));
}

// k_edge smem byte offsets (dynamic smem, 64512 B total)
#define SM_IDX  0         // 256 ints (1024 B)
#define SM_SRED 1024      // 256 floats (1024 B)
#define SM_W    2048      // 64 rows x 72 halves packed  (9216 B)
#define SM_A    11264     // 128 rows x 72 halves        (18432 B)
#define SM_D    29696     // 128 rows x 68 floats        (34816 B)
#define SM_EDGE_TOTAL 64512

// ---------------- K0a / K0b: zero accumulators (keeps k_edge at launch 3) ---
__global__ void __launch_bounds__(256) k_zero_a() {
    int stride = gridDim.x * blockDim.x;
    for (int i = blockIdx.x * blockDim.x + threadIdx.x; i < NN*DD; i += stride)
        g_sumh[i] = 0.f;
    int t = blockIdx.x * blockDim.x + threadIdx.x;
    if (t < 256) g_stats[t] = 0.f;
}
__global__ void __launch_bounds__(256) k_zero_b() {
    int stride = gridDim.x * blockDim.x;
    for (int i = blockIdx.x * blockDim.x + threadIdx.x; i < NN*DD; i += stride)
        g_sums[i] = 0.f;
}

// ---------------- K1: node GEMMs (e_src, e_dst, Bh, xs), f32x2 --------------
__global__ void __launch_bounds__(256, 2) k_node_gemm(
    const float* __restrict__ nf,
    const float* __restrict__ Wsg, const float* __restrict__ bsg,
    const float* __restrict__ Wdg, const float* __restrict__ bdg,
    const float* __restrict__ Wdu, const float* __restrict__ bdu,
    const float* __restrict__ Wsu, const float* __restrict__ bsu)
{
    extern __shared__ float sm[];
    float* sW    = sm;            // 16384 floats
    float* srow2 = sm + 16384;    // 8192 floats
    int tid = threadIdx.x;
    int tx = tid & 15, ty = tid >> 4;

    for (int i = tid; i < 4096; i += 256) {
        sW[i]         = Wsg[i];
        sW[4096 + i]  = Wdg[i];
        sW[8192 + i]  = Wdu[i];
        sW[12288 + i] = Wsu[i];
    }
    u64 bias[4][2];
    bias[0][0] = pack2(bsg[tx*4], bsg[tx*4+1]); bias[0][1] = pack2(bsg[tx*4+2], bsg[tx*4+3]);
    bias[1][0] = pack2(bdg[tx*4], bdg[tx*4+1]); bias[1][1] = pack2(bdg[tx*4+2], bdg[tx*4+3]);
    bias[2][0] = pack2(bdu[tx*4], bdu[tx*4+1]); bias[2][1] = pack2(bdu[tx*4+2], bdu[tx*4+3]);
    bias[3][0] = pack2(bsu[tx*4], bsu[tx*4+1]); bias[3][1] = pack2(bsu[tx*4+2], bsu[tx*4+3]);

    int nchunk = (NN + 63) / 64;
    for (int c = blockIdx.x; c < nchunk; c += gridDim.x) {
        int base = c * 64;
        __syncthreads();
        #pragma unroll
        for (int l = 0; l < 4; l++) {
            int idx = tid + l * 256;
            int r = idx >> 4, c4 = (idx & 15) * 4;
            int row = base + r;
            float4 v = make_float4(0.f, 0.f, 0.f, 0.f);
            if (row < NN) v = *(const float4*)(nf + row*64 + c4);
            float* d = srow2 + r*128 + c4*2;
            ((float4*)d)[0] = make_float4(v.x, v.x, v.y, v.y);
            ((float4*)d)[1] = make_float4(v.z, v.z, v.w, v.w);
        }
        __syncthreads();

        u64 acc[4][4][2];
        #pragma unroll
        for (int j = 0; j < 4; j++)
            #pragma unroll
            for (int r = 0; r < 4; r++) { acc[j][r][0] = bias[j][0]; acc[j][r][1] = bias[j][1]; }

        const float* wp = sW + tx*4;
        #pragma unroll 4
        for (int k = 0; k < 64; k += 2) {
            ulonglong2 A[4];
            #pragma unroll
            for (int r = 0; r < 4; r++)
                A[r] = *(const ulonglong2*)(srow2 + (ty*4+r)*128 + k*2);
            #pragma unroll
            for (int j = 0; j < 4; j++) {
                ulonglong2 W0 = *(const ulonglong2*)(wp + j*4096 + k*64);
                ulonglong2 W1 = *(const ulonglong2*)(wp + j*4096 + (k+1)*64);
                #pragma unroll
                for (int r = 0; r < 4; r++) {
                    ffma2(acc[j][r][0], A[r].x, W0.x);
                    ffma2(acc[j][r][1], A[r].x, W0.y);
                    ffma2(acc[j][r][0], A[r].y, W1.x);
                    ffma2(acc[j][r][1], A[r].y, W1.y);
                }
            }
        }
        #pragma unroll
        for (int r = 0; r < 4; r++) {
            int row = base + ty*4 + r;
            if (row < NN) {
                int off = row*64 + tx*4;
                float2 a0, a1;
                a0 = unpack2(acc[0][r][0]); a1 = unpack2(acc[0][r][1]);
                *(float4*)&g_esrc[off] = make_float4(a0.x, a0.y, a1.x, a1.y);
                a0 = unpack2(acc[1][r][0]); a1 = unpack2(acc[1][r][1]);
                *(float4*)&g_edst[off] = make_float4(a0.x, a0.y, a1.x, a1.y);
                a0 = unpack2(acc[2][r][0]); a1 = unpack2(acc[2][r][1]);
                *(float4*)&g_Bh[off]   = make_float4(a0.x, a0.y, a1.x, a1.y);
                a0 = unpack2(acc[3][r][0]); a1 = unpack2(acc[3][r][1]);
                *(float4*)&g_xs[off]   = make_float4(a0.x, a0.y, a1.x, a1.y);
            }
        }
    }
}

// ---------------- K2: edge kernel — mma.sync f16 GEMM + fused epilogue ------
// 128 edges/chunk. Warp w computes rows w*16..w*16+15 (4 k-steps x 8 n-tiles
// of m16n8k16). A fp16 in smem (rows padded to 72 halves); B = Weg^T fp16
// packed so one LDS.64 yields a full B fragment. D staged to smem (rows
// padded to 68 floats), consumed by the R7 epilogue.
// (256,3): cap regs at 84 to fit 3 blocks/SM — kernel is latency-bound
// (R11: occ 24.7%, issue 21.8%, all pipes <40%), so spills are cheap and
// +50% resident warps covers the gather/red latency chain.
__global__ void __launch_bounds__(256, 3) k_edge(
    const float* __restrict__ ef, const int* __restrict__ src, const int* __restrict__ dst,
    const float* __restrict__ Weg, const float* __restrict__ beg)
{
    extern __shared__ char smem[];
    int*    sidx = (int*)(smem + SM_IDX);
    float*  sred = (float*)(smem + SM_SRED);
    __half* sW   = (__half*)(smem + SM_W);
    __half* sA   = (__half*)(smem + SM_A);
    float*  sD   = (float*)(smem + SM_D);

    int tid = threadIdx.x;
    int wid = tid >> 5, lane = tid & 31;
    int tig = lane & 3, grp = lane >> 2;
    int tx = tid & 15, ty = tid >> 4;

    // W fill: packed so B frag (b0,b1) = one 8-byte load.
    for (int i = tid; i < 4096; i += 256) {
        int k = i >> 6, n = i & 63;
        int s = k >> 4, r = k & 15;
        int q = (r & 7) >> 1, hi = r >> 3, lo = r & 1;
        sW[n*72 + s*16 + q*4 + hi*2 + lo] = __float2half_rn(Weg[i]);
    }
    float4 bb = *(const float4*)(beg + tx*4);

    float ls[4] = {0.f,0.f,0.f,0.f};
    float lq[4] = {0.f,0.f,0.f,0.f};

    int nchunk = EE / 128;    // 6250
    for (int c = blockIdx.x; c < nchunk; c += gridDim.x) {
        int base = c * 128;
        __syncthreads();      // prev epilogue done (sA/sidx reuse)
        #pragma unroll
        for (int l = 0; l < 8; l++) {
            int idx = tid + l * 256;             // float4 index 0..2047
            int r = idx >> 4, c4 = (idx & 15) * 4;
            float4 v = *(const float4*)(ef + (base + r)*64 + c4);
            __half2 h0 = __floats2half2_rn(v.x, v.y);
            __half2 h1 = __floats2half2_rn(v.z, v.w);
            *(uint2*)(sA + r*72 + c4) = make_uint2(h2bits(h0), h2bits(h1));
        }
        if (tid < 128) sidx[tid] = src[base + tid];
        else           sidx[tid] = dst[base + tid - 128];
        __syncthreads();

        float acc[8][4];
        #pragma unroll
        for (int j = 0; j < 8; j++) {
            acc[j][0] = 0.f; acc[j][1] = 0.f; acc[j][2] = 0.f; acc[j][3] = 0.f;
        }

        const __half* arow = sA + (wid*16 + grp)*72;
        #pragma unroll
        for (int s = 0; s < 4; s++) {
            int k0 = s*16 + tig*2;
            uint32_t a0 = *(const uint32_t*)(arow + k0);
            uint32_t a1 = *(const uint32_t*)(arow + 8*72 + k0);
            uint32_t a2 = *(const uint32_t*)(arow + k0 + 8);
            uint32_t a3 = *(const uint32_t*)(arow + 8*72 + k0 + 8);
            #pragma unroll
            for (int j = 0; j < 8; j++) {
                uint2 b = *(const uint2*)(sW + (j*8 + grp)*72 + s*16 + tig*4);
                mma_16816(acc[j], a0, a1, a2, a3, b.x, b.y);
            }
        }

        // stage D to smem
        float* drow = sD + (wid*16 + grp)*68;
        #pragma unroll
        for (int j = 0; j < 8; j++) {
            *(float2*)(drow + j*8 + tig*2)        = make_float2(acc[j][0], acc[j][1]);
            *(float2*)(drow + 8*68 + j*8 + tig*2) = make_float2(acc[j][2], acc[j][3]);
        }
        __syncthreads();

        // epilogue (R7 mapping: ty -> 8 rows, tx -> col quad)
        #pragma unroll
        for (int r = 0; r < 8; r++) {
            int row = ty*8 + r;
            int e = base + row;
            int s = sidx[row], t = sidx[128 + row];
            const int soff = s*64 + tx*4;
            const int toff = t*64 + tx*4;
            float4 dv = *(const float4*)(sD + row*68 + tx*4);
            float4 es = *(const float4*)&g_esrc[soff];
            float4 ed = *(const float4*)&g_edst[toff];
            float4 m;
            m.x = dv.x + bb.x + es.x + ed.x;
            m.y = dv.y + bb.y + es.y + ed.y;
            m.z = dv.z + bb.z + es.z + ed.z;
            m.w = dv.w + bb.w + es.w + ed.w;

            __half2 h0 = __floats2half2_rn(m.x, m.y);
            __half2 h1 = __floats2half2_rn(m.z, m.w);
            *(uint2*)(g_mh + (size_t)e*64 + tx*4) = make_uint2(h2bits(h0), h2bits(h1));

            ls[0] += m.x; lq[0] += m.x*m.x;
            ls[1] += m.y; lq[1] += m.y*m.y;
            ls[2] += m.z; lq[2] += m.z*m.z;
            ls[3] += m.w; lq[3] += m.w*m.w;

            float4 bh = *(const float4*)&g_Bh[soff];
            float sg0 = fsigmoid(m.x), sg1 = fsigmoid(m.y);
            float sg2 = fsigmoid(m.z), sg3 = fsigmoid(m.w);
            red_add_v4(&g_sums[toff], sg0, sg1, sg2, sg3);
            red_add_v4(&g_sumh[toff], bh.x*sg0, bh.y*sg1, bh.z*sg2, bh.w*sg3);
        }
    }

    // block-level BN stats reduction: feature d = tx*4 + comp, reduce over ty
    #pragma unroll
    for (int comp = 0; comp < 4; comp++) {
        __syncthreads();
        sred[tid] = ls[comp];
        __syncthreads();
        if (ty == 0) {
            float ssum = 0.f;
            #pragma unroll
            for (int j = 0; j < 16; j++) ssum += sred[j*16 + tx];
            atomicAdd(&g_stats[tx*4 + comp], ssum);
        }
        __syncthreads();
        sred[tid] = lq[comp];
        __syncthreads();
        if (ty == 0) {
            float ssum = 0.f;
            #pragma unroll
            for (int j = 0; j < 16; j++) ssum += sred[j*16 + tx];
            atomicAdd(&g_stats[64 + tx*4 + comp], ssum);
        }
    }
}

// ---------------- K3: node finalize: x_pre = xs + h, node-BN stats -----------
__global__ void __launch_bounds__(256) k_node_fin() {
    int tid = threadIdx.x;
    int d = tid & 63;
    int stride = gridDim.x * 256;
    float lsum = 0.f, lsq = 0.f;
    for (int i = blockIdx.x * 256 + tid; i < NN*DD; i += stride) {
        float xp = g_xs[i] + g_sumh[i] / (g_sums[i] + 1e-6f);
        g_xs[i] = xp;
        lsum += xp; lsq += xp*xp;
    }
    __shared__ float sred[256];
    sred[tid] = lsum;
    __syncthreads();
    if (tid < 64)
        atomicAdd(&g_stats[128 + d], sred[d] + sred[64+d] + sred[128+d] + sred[192+d]);
    __syncthreads();
    sred[tid] = lsq;
    __syncthreads();
    if (tid < 64)
        atomicAdd(&g_stats[192 + d], sred[d] + sred[64+d] + sred[128+d] + sred[192+d]);
}

// ---------------- K4: BN scale/shift ----------------------------------------
__global__ void k_bn(const float* __restrict__ gn, const float* __restrict__ btn,
                     const float* __restrict__ ge, const float* __restrict__ bte)
{
    int d = threadIdx.x;   // 64 threads
    float me = g_stats[d] * (1.f / EE);
    float ve = g_stats[64 + d] * (1.f / EE) - me * me;
    float se = ge[d] * rsqrtf(ve + 1e-5f);
    g_bn[128 + d] = se;
    g_bn[192 + d] = bte[d] - me * se;

    float mn = g_stats[128 + d] * (1.f / NN);
    float vn = g_stats[192 + d] * (1.f / NN) - mn * mn;
    float sn = gn[d] * rsqrtf(vn + 1e-5f);
    g_bn[d]      = sn;
    g_bn[64 + d] = btn[d] - mn * sn;
}

// ---------------- K5: node output -------------------------------------------
__global__ void __launch_bounds__(256) k_node_out(const float* __restrict__ nf,
                                                  float* __restrict__ out)
{
    int i4 = blockIdx.x * 256 + threadIdx.x;
    if (i4 >= NN*DD/4) return;
    int d4 = (i4 & 15) * 4;
    float4 sc = *(const float4*)&g_bn[d4];
    float4 sh = *(const float4*)&g_bn[64 + d4];
    float4 xp = *(const float4*)&g_xs[i4*4];
    float4 bs = *(const float4*)&nf[i4*4];
    float4 o;
    o.x = bs.x + fsilu(xp.x*sc.x + sh.x);
    o.y = bs.y + fsilu(xp.y*sc.y + sh.y);
    o.z = bs.z + fsilu(xp.z*sc.z + sh.z);
    o.w = bs.w + fsilu(xp.w*sc.w + sh.w);
    *(float4*)&out[i4*4] = o;
}

// ---------------- K6: edge output (fp16 m) -----------------------------------
__global__ void __launch_bounds__(256) k_edge_out(const float* __restrict__ ef,
                                                  float* __restrict__ out)
{
    int stride = gridDim.x * 256;
    for (int i4 = blockIdx.x * 256 + threadIdx.x; i4 < EE*DD/4; i4 += stride) {
        int d4 = (i4 & 15) * 4;
        float4 sc = *(const float4*)&g_bn[128 + d4];
        float4 sh = *(const float4*)&g_bn[192 + d4];
        uint2 pk = *(const uint2*)(g_mh + (size_t)i4*4);
        __half2 h0 = *(__half2*)&pk.x;
        __half2 h1 = *(__half2*)&pk.y;
        float2 m01 = __half22float2(h0);
        float2 m23 = __half22float2(h1);
        float4 bs = *(const float4*)&ef[i4*4];
        float4 o;
        o.x = bs.x + fsilu(m01.x*sc.x + sh.x);
        o.y = bs.y + fsilu(m01.y*sc.y + sh.y);
        o.z = bs.z + fsilu(m23.x*sc.z + sh.z);
        o.w = bs.w + fsilu(m23.y*sc.w + sh.w);
        *(float4*)&out[i4*4] = o;
    }
}

// ---------------- launcher ---------------------------------------------------
extern "C" void kernel_launch(void* const* d_in, const int* in_sizes, int n_in,
                              void* d_out, int out_size)
{
    const float* nf  = (const float*)d_in[0];
    const float* ef  = (const float*)d_in[1];
    const int*   src = (const int*)  d_in[2];
    const int*   dst = (const int*)  d_in[3];
    const float *Wsg = (const float*)d_in[4],  *bsg = (const float*)d_in[5];
    const float *Wdg = (const float*)d_in[6],  *bdg = (const float*)d_in[7];
    const float *Weg = (const float*)d_in[8],  *beg = (const float*)d_in[9];
    const float *Wsu = (const float*)d_in[10], *bsu = (const float*)d_in[11];
    const float *Wdu = (const float*)d_in[12], *bdu = (const float*)d_in[13];
    const float *gn  = (const float*)d_in[14], *btn = (const float*)d_in[15];
    const float *ge  = (const float*)d_in[16], *bte = (const float*)d_in[17];
    float* out = (float*)d_out;

    static const size_t k1_smem = (16384 + 8192) * sizeof(float);   // 96 KB
    cudaFuncSetAttribute(k_node_gemm, cudaFuncAttributeMaxDynamicSharedMemorySize,
                         (int)k1_smem);
    cudaFuncSetAttribute(k_edge, cudaFuncAttributeMaxDynamicSharedMemorySize,
                         SM_EDGE_TOTAL);

    k_zero_a<<<1024, 256>>>();                                        // launch 0
    k_node_gemm<<<592, 256, k1_smem>>>(nf, Wsg, bsg, Wdg, bdg,
                                       Wdu, bdu, Wsu, bsu);           // launch 1
    k_zero_b<<<1024, 256>>>();                                        // launch 2
    k_edge<<<2960, 256, SM_EDGE_TOTAL>>>(ef, src, dst, Weg, beg);     // launch 3 (profiled)
    k_node_fin<<<1024, 256>>>();                                      // launch 4
    k_bn<<<1, 64>>>(gn, btn, ge, bte);                                // launch 5
    k_node_out<<<3125, 256>>>(nf, out);                               // launch 6
    k_edge_out<<<8192, 256>>>(ef, out + NN*DD);                       // launch 7
}

// round 13
// speedup vs baseline: 2.0056x; 1.0877x over previous
#include <cuda_runtime.h>
#include <cuda_fp16.h>
#include <math.h>
#include <cstdint>

#define NN 50000
#define EE 800000
#define DD 64

typedef unsigned long long u64;

// ---------------- scratch (static device globals; no runtime allocation) ----
__device__ __align__(16) float g_esrc[NN*DD];
__device__ __align__(16) float g_edst[NN*DD];
__device__ __align__(16) float g_Bh[NN*DD];
__device__ __align__(16) float g_xs[NN*DD];      // xs, then x_pre in-place
__device__ __align__(16) __half g_mh[EE*DD];     // m stored fp16 (102.4 MB)
__device__ __align__(16) float g_sumh[NN*DD];
__device__ __align__(16) float g_sums[NN*DD];
// stats: [0..63] e_sum, [64..127] e_sumsq, [128..191] n_sum, [192..255] n_sumsq
__device__ __align__(16) float g_stats[256];
// bn params: [0..63] scale_n, [64..127] shift_n, [128..191] scale_e, [192..255] shift_e
__device__ __align__(16) float g_bn[256];

__device__ __forceinline__ float fsigmoid(float x) { return 1.f / (1.f + __expf(-x)); }
__device__ __forceinline__ float fsilu(float z)    { return z / (1.f + __expf(-z)); }
__device__ __forceinline__ unsigned h2bits(__half2 h) { return *(unsigned*)&h; }

// packed dual-lane fp32 fma (node GEMM)
__device__ __forceinline__ void ffma2(u64& acc, u64 a, u64 b) {
    asm("fma.rn.f32x2 %0, %1, %2, %0;" : "+l"(acc) : "l"(a), "l"(b));
}
__device__ __forceinline__ u64 pack2(float x, float y) {
    float2 t = make_float2(x, y); return *(u64*)&t;
}
__device__ __forceinline__ float2 unpack2(u64 v) { return *(float2*)&v; }

// vectorized no-return fp32 reduction: 1 instruction, 16 bytes, 4 lanes
__device__ __forceinline__ void red_add_v4(float* addr, float a, float b, float c, float d) {
    asm volatile("red.global.add.v4.f32 [%0], {%1,%2,%3,%4};"
                 :: "l"(addr), "f"(a), "f"(b), "f"(c), "f"(d) : "memory");
}

// warp-level tensor-core mma (baseline PTX, valid on sm_103 non-'a' target)
__device__ __forceinline__ void mma_16816(float* c, uint32_t a0, uint32_t a1,
                                          uint32_t a2, uint32_t a3,
                                          uint32_t b0, uint32_t b1) {
    asm volatile(
        "mma.sync.aligned.m16n8k16.row.col.f32.f16.f16.f32 "
        "{%0,%1,%2,%3}, {%4,%5,%6,%7}, {%8,%9}, {%0,%1,%2,%3};"
        : "+f"(c[0]), "+f"(c[1]), "+f"(c[2]), "+f"(c[3])
        : "r"(a0), "r"(a1), "r"(a2), "r"(a3), "r"(b0), "r"(b1));
}

// k_edge smem byte offsets (dynamic smem, 48128 B total -> 4 blocks/SM)
#define SM_IDX  0         // 256 ints (1024 B)
#define SM_SRED 1024      // 256 floats (1024 B)
#define SM_W    2048      // 64 rows x 72 halves packed  (9216 B)
#define SM_A    11264     // 128 rows x 72 halves        (18432 B)
#define SM_D    29696     // 128 rows x 72 halves (fp16 D stage, 18432 B)
#define SM_EDGE_TOTAL 48128

// ---------------- K0a / K0b: zero accumulators (keeps k_edge at launch 3) ---
__global__ void __launch_bounds__(256) k_zero_a() {
    int stride = gridDim.x * blockDim.x;
    for (int i = blockIdx.x * blockDim.x + threadIdx.x; i < NN*DD; i += stride)
        g_sumh[i] = 0.f;
    int t = blockIdx.x * blockDim.x + threadIdx.x;
    if (t < 256) g_stats[t] = 0.f;
}
__global__ void __launch_bounds__(256) k_zero_b() {
    int stride = gridDim.x * blockDim.x;
    for (int i = blockIdx.x * blockDim.x + threadIdx.x; i < NN*DD; i += stride)
        g_sums[i] = 0.f;
}

// ---------------- K1: node GEMMs (e_src, e_dst, Bh, xs), f32x2 --------------
__global__ void __launch_bounds__(256, 2) k_node_gemm(
    const float* __restrict__ nf,
    const float* __restrict__ Wsg, const float* __restrict__ bsg,
    const float* __restrict__ Wdg, const float* __restrict__ bdg,
    const float* __restrict__ Wdu, const float* __restrict__ bdu,
    const float* __restrict__ Wsu, const float* __restrict__ bsu)
{
    extern __shared__ float sm[];
    float* sW    = sm;            // 16384 floats
    float* srow2 = sm + 16384;    // 8192 floats
    int tid = threadIdx.x;
    int tx = tid & 15, ty = tid >> 4;

    for (int i = tid; i < 4096; i += 256) {
        sW[i]         = Wsg[i];
        sW[4096 + i]  = Wdg[i];
        sW[8192 + i]  = Wdu[i];
        sW[12288 + i] = Wsu[i];
    }
    u64 bias[4][2];
    bias[0][0] = pack2(bsg[tx*4], bsg[tx*4+1]); bias[0][1] = pack2(bsg[tx*4+2], bsg[tx*4+3]);
    bias[1][0] = pack2(bdg[tx*4], bdg[tx*4+1]); bias[1][1] = pack2(bdg[tx*4+2], bdg[tx*4+3]);
    bias[2][0] = pack2(bdu[tx*4], bdu[tx*4+1]); bias[2][1] = pack2(bdu[tx*4+2], bdu[tx*4+3]);
    bias[3][0] = pack2(bsu[tx*4], bsu[tx*4+1]); bias[3][1] = pack2(bsu[tx*4+2], bsu[tx*4+3]);

    int nchunk = (NN + 63) / 64;
    for (int c = blockIdx.x; c < nchunk; c += gridDim.x) {
        int base = c * 64;
        __syncthreads();
        #pragma unroll
        for (int l = 0; l < 4; l++) {
            int idx = tid + l * 256;
            int r = idx >> 4, c4 = (idx & 15) * 4;
            int row = base + r;
            float4 v = make_float4(0.f, 0.f, 0.f, 0.f);
            if (row < NN) v = *(const float4*)(nf + row*64 + c4);
            float* d = srow2 + r*128 + c4*2;
            ((float4*)d)[0] = make_float4(v.x, v.x, v.y, v.y);
            ((float4*)d)[1] = make_float4(v.z, v.z, v.w, v.w);
        }
        __syncthreads();

        u64 acc[4][4][2];
        #pragma unroll
        for (int j = 0; j < 4; j++)
            #pragma unroll
            for (int r = 0; r < 4; r++) { acc[j][r][0] = bias[j][0]; acc[j][r][1] = bias[j][1]; }

        const float* wp = sW + tx*4;
        #pragma unroll 4
        for (int k = 0; k < 64; k += 2) {
            ulonglong2 A[4];
            #pragma unroll
            for (int r = 0; r < 4; r++)
                A[r] = *(const ulonglong2*)(srow2 + (ty*4+r)*128 + k*2);
            #pragma unroll
            for (int j = 0; j < 4; j++) {
                ulonglong2 W0 = *(const ulonglong2*)(wp + j*4096 + k*64);
                ulonglong2 W1 = *(const ulonglong2*)(wp + j*4096 + (k+1)*64);
                #pragma unroll
                for (int r = 0; r < 4; r++) {
                    ffma2(acc[j][r][0], A[r].x, W0.x);
                    ffma2(acc[j][r][1], A[r].x, W0.y);
                    ffma2(acc[j][r][0], A[r].y, W1.x);
                    ffma2(acc[j][r][1], A[r].y, W1.y);
                }
            }
        }
        #pragma unroll
        for (int r = 0; r < 4; r++) {
            int row = base + ty*4 + r;
            if (row < NN) {
                int off = row*64 + tx*4;
                float2 a0, a1;
                a0 = unpack2(acc[0][r][0]); a1 = unpack2(acc[0][r][1]);
                *(float4*)&g_esrc[off] = make_float4(a0.x, a0.y, a1.x, a1.y);
                a0 = unpack2(acc[1][r][0]); a1 = unpack2(acc[1][r][1]);
                *(float4*)&g_edst[off] = make_float4(a0.x, a0.y, a1.x, a1.y);
                a0 = unpack2(acc[2][r][0]); a1 = unpack2(acc[2][r][1]);
                *(float4*)&g_Bh[off]   = make_float4(a0.x, a0.y, a1.x, a1.y);
                a0 = unpack2(acc[3][r][0]); a1 = unpack2(acc[3][r][1]);
                *(float4*)&g_xs[off]   = make_float4(a0.x, a0.y, a1.x, a1.y);
            }
        }
    }
}

// ---------------- K2: edge kernel — mma.sync f16 GEMM + fused epilogue ------
// 128 edges/chunk. Warp w computes rows w*16..w*16+15 (4 k-steps x 8 n-tiles
// of m16n8k16). A fp16 in smem (rows padded to 72 halves); B = Weg^T fp16
// packed so one LDS.64 yields a full B fragment. D staged to smem as fp16
// (rows padded to 72 halves) to fit 4 blocks/SM; epilogue = R7 mapping.
// (256,4): 64 regs — kernel is latency-bound (R12: occ 35.6%, issue 28.2%),
// spill cost in the epilogue is cheap, +33% resident warps covers latency.
__global__ void __launch_bounds__(256, 4) k_edge(
    const float* __restrict__ ef, const int* __restrict__ src, const int* __restrict__ dst,
    const float* __restrict__ Weg, const float* __restrict__ beg)
{
    extern __shared__ char smem[];
    int*    sidx = (int*)(smem + SM_IDX);
    float*  sred = (float*)(smem + SM_SRED);
    __half* sW   = (__half*)(smem + SM_W);
    __half* sA   = (__half*)(smem + SM_A);
    __half* sD   = (__half*)(smem + SM_D);

    int tid = threadIdx.x;
    int wid = tid >> 5, lane = tid & 31;
    int tig = lane & 3, grp = lane >> 2;
    int tx = tid & 15, ty = tid >> 4;

    // W fill: packed so B frag (b0,b1) = one 8-byte load.
    for (int i = tid; i < 4096; i += 256) {
        int k = i >> 6, n = i & 63;
        int s = k >> 4, r = k & 15;
        int q = (r & 7) >> 1, hi = r >> 3, lo = r & 1;
        sW[n*72 + s*16 + q*4 + hi*2 + lo] = __float2half_rn(Weg[i]);
    }
    float4 bb = *(const float4*)(beg + tx*4);

    float ls[4] = {0.f,0.f,0.f,0.f};
    float lq[4] = {0.f,0.f,0.f,0.f};

    int nchunk = EE / 128;    // 6250
    for (int c = blockIdx.x; c < nchunk; c += gridDim.x) {
        int base = c * 128;
        __syncthreads();      // prev epilogue done (sA/sidx reuse)
        #pragma unroll
        for (int l = 0; l < 8; l++) {
            int idx = tid + l * 256;             // float4 index 0..2047
            int r = idx >> 4, c4 = (idx & 15) * 4;
            float4 v = *(const float4*)(ef + (base + r)*64 + c4);
            __half2 h0 = __floats2half2_rn(v.x, v.y);
            __half2 h1 = __floats2half2_rn(v.z, v.w);
            *(uint2*)(sA + r*72 + c4) = make_uint2(h2bits(h0), h2bits(h1));
        }
        if (tid < 128) sidx[tid] = src[base + tid];
        else           sidx[tid] = dst[base + tid - 128];
        __syncthreads();

        float acc[8][4];
        #pragma unroll
        for (int j = 0; j < 8; j++) {
            acc[j][0] = 0.f; acc[j][1] = 0.f; acc[j][2] = 0.f; acc[j][3] = 0.f;
        }

        const __half* arow = sA + (wid*16 + grp)*72;
        #pragma unroll
        for (int s = 0; s < 4; s++) {
            int k0 = s*16 + tig*2;
            uint32_t a0 = *(const uint32_t*)(arow + k0);
            uint32_t a1 = *(const uint32_t*)(arow + 8*72 + k0);
            uint32_t a2 = *(const uint32_t*)(arow + k0 + 8);
            uint32_t a3 = *(const uint32_t*)(arow + 8*72 + k0 + 8);
            #pragma unroll
            for (int j = 0; j < 8; j++) {
                uint2 b = *(const uint2*)(sW + (j*8 + grp)*72 + s*16 + tig*4);
                mma_16816(acc[j], a0, a1, a2, a3, b.x, b.y);
            }
        }

        // stage D to smem as fp16
        __half* drow = sD + (wid*16 + grp)*72;
        #pragma unroll
        for (int j = 0; j < 8; j++) {
            *(uint32_t*)(drow + j*8 + tig*2)        = h2bits(__floats2half2_rn(acc[j][0], acc[j][1]));
            *(uint32_t*)(drow + 8*72 + j*8 + tig*2) = h2bits(__floats2half2_rn(acc[j][2], acc[j][3]));
        }
        __syncthreads();

        // epilogue (R7 mapping: ty -> 8 rows, tx -> col quad)
        #pragma unroll
        for (int r = 0; r < 8; r++) {
            int row = ty*8 + r;
            int e = base + row;
            int s = sidx[row], t = sidx[128 + row];
            const int soff = s*64 + tx*4;
            const int toff = t*64 + tx*4;
            uint2 dpk = *(const uint2*)(sD + row*72 + tx*4);
            float2 d01 = __half22float2(*(__half2*)&dpk.x);
            float2 d23 = __half22float2(*(__half2*)&dpk.y);
            float4 es = *(const float4*)&g_esrc[soff];
            float4 ed = *(const float4*)&g_edst[toff];
            float4 m;
            m.x = d01.x + bb.x + es.x + ed.x;
            m.y = d01.y + bb.y + es.y + ed.y;
            m.z = d23.x + bb.z + es.z + ed.z;
            m.w = d23.y + bb.w + es.w + ed.w;

            __half2 h0 = __floats2half2_rn(m.x, m.y);
            __half2 h1 = __floats2half2_rn(m.z, m.w);
            *(uint2*)(g_mh + (size_t)e*64 + tx*4) = make_uint2(h2bits(h0), h2bits(h1));

            ls[0] += m.x; lq[0] += m.x*m.x;
            ls[1] += m.y; lq[1] += m.y*m.y;
            ls[2] += m.z; lq[2] += m.z*m.z;
            ls[3] += m.w; lq[3] += m.w*m.w;

            float4 bh = *(const float4*)&g_Bh[soff];
            float sg0 = fsigmoid(m.x), sg1 = fsigmoid(m.y);
            float sg2 = fsigmoid(m.z), sg3 = fsigmoid(m.w);
            red_add_v4(&g_sums[toff], sg0, sg1, sg2, sg3);
            red_add_v4(&g_sumh[toff], bh.x*sg0, bh.y*sg1, bh.z*sg2, bh.w*sg3);
        }
    }

    // block-level BN stats reduction: feature d = tx*4 + comp, reduce over ty
    #pragma unroll
    for (int comp = 0; comp < 4; comp++) {
        __syncthreads();
        sred[tid] = ls[comp];
        __syncthreads();
        if (ty == 0) {
            float ssum = 0.f;
            #pragma unroll
            for (int j = 0; j < 16; j++) ssum += sred[j*16 + tx];
            atomicAdd(&g_stats[tx*4 + comp], ssum);
        }
        __syncthreads();
        sred[tid] = lq[comp];
        __syncthreads();
        if (ty == 0) {
            float ssum = 0.f;
            #pragma unroll
            for (int j = 0; j < 16; j++) ssum += sred[j*16 + tx];
            atomicAdd(&g_stats[64 + tx*4 + comp], ssum);
        }
    }
}

// ---------------- K3: node finalize: x_pre = xs + h, node-BN stats -----------
__global__ void __launch_bounds__(256) k_node_fin() {
    int tid = threadIdx.x;
    int d = tid & 63;
    int stride = gridDim.x * 256;
    float lsum = 0.f, lsq = 0.f;
    for (int i = blockIdx.x * 256 + tid; i < NN*DD; i += stride) {
        float xp = g_xs[i] + g_sumh[i] / (g_sums[i] + 1e-6f);
        g_xs[i] = xp;
        lsum += xp; lsq += xp*xp;
    }
    __shared__ float sred[256];
    sred[tid] = lsum;
    __syncthreads();
    if (tid < 64)
        atomicAdd(&g_stats[128 + d], sred[d] + sred[64+d] + sred[128+d] + sred[192+d]);
    __syncthreads();
    sred[tid] = lsq;
    __syncthreads();
    if (tid < 64)
        atomicAdd(&g_stats[192 + d], sred[d] + sred[64+d] + sred[128+d] + sred[192+d]);
}

// ---------------- K4: BN scale/shift ----------------------------------------
__global__ void k_bn(const float* __restrict__ gn, const float* __restrict__ btn,
                     const float* __restrict__ ge, const float* __restrict__ bte)
{
    int d = threadIdx.x;   // 64 threads
    float me = g_stats[d] * (1.f / EE);
    float ve = g_stats[64 + d] * (1.f / EE) - me * me;
    float se = ge[d] * rsqrtf(ve + 1e-5f);
    g_bn[128 + d] = se;
    g_bn[192 + d] = bte[d] - me * se;

    float mn = g_stats[128 + d] * (1.f / NN);
    float vn = g_stats[192 + d] * (1.f / NN) - mn * mn;
    float sn = gn[d] * rsqrtf(vn + 1e-5f);
    g_bn[d]      = sn;
    g_bn[64 + d] = btn[d] - mn * sn;
}

// ---------------- K5: node output -------------------------------------------
__global__ void __launch_bounds__(256) k_node_out(const float* __restrict__ nf,
                                                  float* __restrict__ out)
{
    int i4 = blockIdx.x * 256 + threadIdx.x;
    if (i4 >= NN*DD/4) return;
    int d4 = (i4 & 15) * 4;
    float4 sc = *(const float4*)&g_bn[d4];
    float4 sh = *(const float4*)&g_bn[64 + d4];
    float4 xp = *(const float4*)&g_xs[i4*4];
    float4 bs = *(const float4*)&nf[i4*4];
    float4 o;
    o.x = bs.x + fsilu(xp.x*sc.x + sh.x);
    o.y = bs.y + fsilu(xp.y*sc.y + sh.y);
    o.z = bs.z + fsilu(xp.z*sc.z + sh.z);
    o.w = bs.w + fsilu(xp.w*sc.w + sh.w);
    *(float4*)&out[i4*4] = o;
}

// ---------------- K6: edge output (fp16 m) -----------------------------------
__global__ void __launch_bounds__(256) k_edge_out(const float* __restrict__ ef,
                                                  float* __restrict__ out)
{
    int stride = gridDim.x * 256;
    for (int i4 = blockIdx.x * 256 + threadIdx.x; i4 < EE*DD/4; i4 += stride) {
        int d4 = (i4 & 15) * 4;
        float4 sc = *(const float4*)&g_bn[128 + d4];
        float4 sh = *(const float4*)&g_bn[192 + d4];
        uint2 pk = *(const uint2*)(g_mh + (size_t)i4*4);
        __half2 h0 = *(__half2*)&pk.x;
        __half2 h1 = *(__half2*)&pk.y;
        float2 m01 = __half22float2(h0);
        float2 m23 = __half22float2(h1);
        float4 bs = *(const float4*)&ef[i4*4];
        float4 o;
        o.x = bs.x + fsilu(m01.x*sc.x + sh.x);
        o.y = bs.y + fsilu(m01.y*sc.y + sh.y);
        o.z = bs.z + fsilu(m23.x*sc.z + sh.z);
        o.w = bs.w + fsilu(m23.y*sc.w + sh.w);
        *(float4*)&out[i4*4] = o;
    }
}

// ---------------- launcher ---------------------------------------------------
extern "C" void kernel_launch(void* const* d_in, const int* in_sizes, int n_in,
                              void* d_out, int out_size)
{
    const float* nf  = (const float*)d_in[0];
    const float* ef  = (const float*)d_in[1];
    const int*   src = (const int*)  d_in[2];
    const int*   dst = (const int*)  d_in[3];
    const float *Wsg = (const float*)d_in[4],  *bsg = (const float*)d_in[5];
    const float *Wdg = (const float*)d_in[6],  *bdg = (const float*)d_in[7];
    const float *Weg = (const float*)d_in[8],  *beg = (const float*)d_in[9];
    const float *Wsu = (const float*)d_in[10], *bsu = (const float*)d_in[11];
    const float *Wdu = (const float*)d_in[12], *bdu = (const float*)d_in[13];
    const float *gn  = (const float*)d_in[14], *btn = (const float*)d_in[15];
    const float *ge  = (const float*)d_in[16], *bte = (const float*)d_in[17];
    float* out = (float*)d_out;

    static const size_t k1_smem = (16384 + 8192) * sizeof(float);   // 96 KB
    cudaFuncSetAttribute(k_node_gemm, cudaFuncAttributeMaxDynamicSharedMemorySize,
                         (int)k1_smem);
    cudaFuncSetAttribute(k_edge, cudaFuncAttributeMaxDynamicSharedMemorySize,
                         SM_EDGE_TOTAL);

    k_zero_a<<<1024, 256>>>();                                        // launch 0
    k_node_gemm<<<592, 256, k1_smem>>>(nf, Wsg, bsg, Wdg, bdg,
                                       Wdu, bdu, Wsu, bsu);           // launch 1
    k_zero_b<<<1024, 256>>>();                                        // launch 2
    k_edge<<<2960, 256, SM_EDGE_TOTAL>>>(ef, src, dst, Weg, beg);     // launch 3 (profiled)
    k_node_fin<<<1024, 256>>>();                                      // launch 4
    k_bn<<<1, 64>>>(gn, btn, ge, bte);                                // launch 5
    k_node_out<<<3125, 256>>>(nf, out);                               // launch 6
    k_edge_out<<<8192, 256>>>(ef, out + NN*DD);                       // launch 7
}

// round 15
// speedup vs baseline: 2.1540x; 1.0740x over previous
#include <cuda_runtime.h>
#include <cuda_fp16.h>
#include <math.h>
#include <cstdint>

#define NN 50000
#define EE 800000
#define DD 64

typedef unsigned long long u64;

// ---------------- scratch (static device globals; no runtime allocation) ----
__device__ __align__(16) float g_esrc[NN*DD];
__device__ __align__(16) float g_edst[NN*DD];
__device__ __align__(16) float g_Bh[NN*DD];
__device__ __align__(16) float g_xs[NN*DD];      // xs, then x_pre in-place
__device__ __align__(16) __half g_mh[EE*DD];     // m stored fp16 (102.4 MB)
__device__ __align__(16) float g_sumh[NN*DD];
__device__ __align__(16) float g_sums[NN*DD];
// stats: [0..63] e_sum, [64..127] e_sumsq, [128..191] n_sum, [192..255] n_sumsq
__device__ __align__(16) float g_stats[256];
// bn params: [0..63] scale_n, [64..127] shift_n, [128..191] scale_e, [192..255] shift_e
__device__ __align__(16) float g_bn[256];

__device__ __forceinline__ float fsigmoid(float x) { return 1.f / (1.f + __expf(-x)); }
__device__ __forceinline__ float fsilu(float z)    { return z / (1.f + __expf(-z)); }
__device__ __forceinline__ unsigned h2bits(__half2 h) { return *(unsigned*)&h; }

// vectorized no-return fp32 reduction: 1 instruction, 16 bytes, 4 lanes
__device__ __forceinline__ void red_add_v4(float* addr, float a, float b, float c, float d) {
    asm volatile("red.global.add.v4.f32 [%0], {%1,%2,%3,%4};"
                 :: "l"(addr), "f"(a), "f"(b), "f"(c), "f"(d) : "memory");
}

// warp-level tensor-core mma (baseline PTX, valid on sm_103 non-'a' target)
__device__ __forceinline__ void mma_16816(float* c, uint32_t a0, uint32_t a1,
                                          uint32_t a2, uint32_t a3,
                                          uint32_t b0, uint32_t b1) {
    asm volatile(
        "mma.sync.aligned.m16n8k16.row.col.f32.f16.f16.f32 "
        "{%0,%1,%2,%3}, {%4,%5,%6,%7}, {%8,%9}, {%0,%1,%2,%3};"
        : "+f"(c[0]), "+f"(c[1]), "+f"(c[2]), "+f"(c[3])
        : "r"(a0), "r"(a1), "r"(a2), "r"(a3), "r"(b0), "r"(b1));
}

// k_edge smem byte offsets (dynamic smem, 48128 B total -> 4 blocks/SM)
#define SM_IDX  0         // 256 ints (1024 B)
#define SM_SRED 1024      // 256 floats (1024 B)
#define SM_W    2048      // 64 rows x 72 halves packed  (9216 B)
#define SM_A    11264     // 128 rows x 72 halves        (18432 B)
#define SM_D    29696     // 128 rows x 72 halves (fp16 D stage, 18432 B)
#define SM_EDGE_TOTAL 48128

// k_node_gemm smem byte offsets (90112 B -> 2 blocks/SM)
#define NG_W    0         // 4 matrices x 64 x 72 halves (36864 B)
#define NG_A    36864     // 128 x 72 halves             (18432 B)
#define NG_D    55296     // 128 x 68 floats             (34816 B)
#define NG_TOTAL 90112

// ---------------- K0a / K0b: tiny kernels (keep k_edge at launch index 3) ---
__global__ void k_zero_a() {
    g_stats[threadIdx.x] = 0.f;           // 256 threads
}
__global__ void k_zero_b() {
    g_bn[threadIdx.x] = 0.f;              // overwritten by k_bn; launch-pad only
}

// ---------------- K1: node GEMMs via mma.sync (e_src, e_dst, Bh, xs) --------
// 128 nodes/chunk, one fp16 A tile reused for 4 weight matrices (sequential,
// 32-reg acc each). Same W-pack / fragment layout as k_edge (proven). Epilogue
// adds bias and stores fp32; matrix 0's epilogue also zeroes g_sums/g_sumh.
__global__ void __launch_bounds__(256, 2) k_node_gemm(
    const float* __restrict__ nf,
    const float* __restrict__ Wsg, const float* __restrict__ bsg,
    const float* __restrict__ Wdg, const float* __restrict__ bdg,
    const float* __restrict__ Wdu, const float* __restrict__ bdu,
    const float* __restrict__ Wsu, const float* __restrict__ bsu)
{
    extern __shared__ char smem[];
    __half* sW = (__half*)(smem + NG_W);
    __half* sA = (__half*)(smem + NG_A);
    float*  sD = (float*)(smem + NG_D);

    int tid = threadIdx.x;
    int wid = tid >> 5, lane = tid & 31;
    int tig = lane & 3, grp = lane >> 2;
    int tx = tid & 15, ty = tid >> 4;

    // pack all 4 weight matrices (k_edge layout per matrix)
    #pragma unroll
    for (int jm = 0; jm < 4; jm++) {
        const float* Wp = (jm == 0) ? Wsg : (jm == 1) ? Wdg : (jm == 2) ? Wdu : Wsu;
        for (int i = tid; i < 4096; i += 256) {
            int k = i >> 6, n = i & 63;
            int s = k >> 4, r = k & 15;
            int q = (r & 7) >> 1, hi = r >> 3, lo = r & 1;
            sW[jm*4608 + n*72 + s*16 + q*4 + hi*2 + lo] = __float2half_rn(Wp[i]);
        }
    }
    float4 bb[4];
    bb[0] = *(const float4*)(bsg + tx*4);
    bb[1] = *(const float4*)(bdg + tx*4);
    bb[2] = *(const float4*)(bdu + tx*4);
    bb[3] = *(const float4*)(bsu + tx*4);

    int nchunk = (NN + 127) / 128;        // 391
    for (int c = blockIdx.x; c < nchunk; c += gridDim.x) {
        int base = c * 128;
        __syncthreads();                  // prev chunk's last epilogue done
        #pragma unroll
        for (int l = 0; l < 8; l++) {
            int idx = tid + l * 256;
            int r = idx >> 4, c4 = (idx & 15) * 4;
            int row = base + r;
            float4 v = make_float4(0.f, 0.f, 0.f, 0.f);
            if (row < NN) v = *(const float4*)(nf + row*64 + c4);
            __half2 h0 = __floats2half2_rn(v.x, v.y);
            __half2 h1 = __floats2half2_rn(v.z, v.w);
            *(uint2*)(sA + r*72 + c4) = make_uint2(h2bits(h0), h2bits(h1));
        }
        __syncthreads();

        #pragma unroll
        for (int jm = 0; jm < 4; jm++) {
            float acc[8][4];
            #pragma unroll
            for (int j = 0; j < 8; j++) {
                acc[j][0] = 0.f; acc[j][1] = 0.f; acc[j][2] = 0.f; acc[j][3] = 0.f;
            }
            const __half* arow  = sA + (wid*16 + grp)*72;
            const __half* wbase = sW + jm*4608;
            #pragma unroll
            for (int s = 0; s < 4; s++) {
                int k0 = s*16 + tig*2;
                uint32_t a0 = *(const uint32_t*)(arow + k0);
                uint32_t a1 = *(const uint32_t*)(arow + 8*72 + k0);
                uint32_t a2 = *(const uint32_t*)(arow + k0 + 8);
                uint32_t a3 = *(const uint32_t*)(arow + 8*72 + k0 + 8);
                #pragma unroll
                for (int j = 0; j < 8; j++) {
                    uint2 b = *(const uint2*)(wbase + (j*8 + grp)*72 + s*16 + tig*4);
                    mma_16816(acc[j], a0, a1, a2, a3, b.x, b.y);
                }
            }

            // stage D (fp32) to smem
            float* drow = sD + (wid*16 + grp)*68;
            #pragma unroll
            for (int j = 0; j < 8; j++) {
                *(float2*)(drow + j*8 + tig*2)        = make_float2(acc[j][0], acc[j][1]);
                *(float2*)(drow + 8*68 + j*8 + tig*2) = make_float2(acc[j][2], acc[j][3]);
            }
            __syncthreads();

            // epilogue: bias + store fp32
            float* outp = (jm == 0) ? g_esrc : (jm == 1) ? g_edst : (jm == 2) ? g_Bh : g_xs;
            #pragma unroll
            for (int r = 0; r < 8; r++) {
                int row = ty*8 + r;
                int nrow = base + row;
                if (nrow < NN) {
                    int off = nrow*64 + tx*4;
                    float4 d = *(const float4*)(sD + row*68 + tx*4);
                    d.x += bb[jm].x; d.y += bb[jm].y; d.z += bb[jm].z; d.w += bb[jm].w;
                    *(float4*)&outp[off] = d;
                    if (jm == 0) {
                        *(float4*)&g_sums[off] = make_float4(0.f, 0.f, 0.f, 0.f);
                        *(float4*)&g_sumh[off] = make_float4(0.f, 0.f, 0.f, 0.f);
                    }
                }
            }
            __syncthreads();              // protect sD before next jm's stage
        }
    }
}

// ---------------- K2: edge kernel — mma.sync f16 GEMM + fused epilogue ------
// (unchanged from R13: 175.7 us, occ 47.9%)
__global__ void __launch_bounds__(256, 4) k_edge(
    const float* __restrict__ ef, const int* __restrict__ src, const int* __restrict__ dst,
    const float* __restrict__ Weg, const float* __restrict__ beg)
{
    extern __shared__ char smem[];
    int*    sidx = (int*)(smem + SM_IDX);
    float*  sred = (float*)(smem + SM_SRED);
    __half* sW   = (__half*)(smem + SM_W);
    __half* sA   = (__half*)(smem + SM_A);
    __half* sD   = (__half*)(smem + SM_D);

    int tid = threadIdx.x;
    int wid = tid >> 5, lane = tid & 31;
    int tig = lane & 3, grp = lane >> 2;
    int tx = tid & 15, ty = tid >> 4;

    // W fill: packed so B frag (b0,b1) = one 8-byte load.
    for (int i = tid; i < 4096; i += 256) {
        int k = i >> 6, n = i & 63;
        int s = k >> 4, r = k & 15;
        int q = (r & 7) >> 1, hi = r >> 3, lo = r & 1;
        sW[n*72 + s*16 + q*4 + hi*2 + lo] = __float2half_rn(Weg[i]);
    }
    float4 bb = *(const float4*)(beg + tx*4);

    float ls[4] = {0.f,0.f,0.f,0.f};
    float lq[4] = {0.f,0.f,0.f,0.f};

    int nchunk = EE / 128;    // 6250
    for (int c = blockIdx.x; c < nchunk; c += gridDim.x) {
        int base = c * 128;
        __syncthreads();      // prev epilogue done (sA/sidx reuse)
        #pragma unroll
        for (int l = 0; l < 8; l++) {
            int idx = tid + l * 256;             // float4 index 0..2047
            int r = idx >> 4, c4 = (idx & 15) * 4;
            float4 v = *(const float4*)(ef + (base + r)*64 + c4);
            __half2 h0 = __floats2half2_rn(v.x, v.y);
            __half2 h1 = __floats2half2_rn(v.z, v.w);
            *(uint2*)(sA + r*72 + c4) = make_uint2(h2bits(h0), h2bits(h1));
        }
        if (tid < 128) sidx[tid] = src[base + tid];
        else           sidx[tid] = dst[base + tid - 128];
        __syncthreads();

        float acc[8][4];
        #pragma unroll
        for (int j = 0; j < 8; j++) {
            acc[j][0] = 0.f; acc[j][1] = 0.f; acc[j][2] = 0.f; acc[j][3] = 0.f;
        }

        const __half* arow = sA + (wid*16 + grp)*72;
        #pragma unroll
        for (int s = 0; s < 4; s++) {
            int k0 = s*16 + tig*2;
            uint32_t a0 = *(const uint32_t*)(arow + k0);
            uint32_t a1 = *(const uint32_t*)(arow + 8*72 + k0);
            uint32_t a2 = *(const uint32_t*)(arow + k0 + 8);
            uint32_t a3 = *(const uint32_t*)(arow + 8*72 + k0 + 8);
            #pragma unroll
            for (int j = 0; j < 8; j++) {
                uint2 b = *(const uint2*)(sW + (j*8 + grp)*72 + s*16 + tig*4);
                mma_16816(acc[j], a0, a1, a2, a3, b.x, b.y);
            }
        }

        // stage D to smem as fp16
        __half* drow = sD + (wid*16 + grp)*72;
        #pragma unroll
        for (int j = 0; j < 8; j++) {
            *(uint32_t*)(drow + j*8 + tig*2)        = h2bits(__floats2half2_rn(acc[j][0], acc[j][1]));
            *(uint32_t*)(drow + 8*72 + j*8 + tig*2) = h2bits(__floats2half2_rn(acc[j][2], acc[j][3]));
        }
        __syncthreads();

        // epilogue (R7 mapping: ty -> 8 rows, tx -> col quad)
        #pragma unroll
        for (int r = 0; r < 8; r++) {
            int row = ty*8 + r;
            int e = base + row;
            int s = sidx[row], t = sidx[128 + row];
            const int soff = s*64 + tx*4;
            const int toff = t*64 + tx*4;
            uint2 dpk = *(const uint2*)(sD + row*72 + tx*4);
            float2 d01 = __half22float2(*(__half2*)&dpk.x);
            float2 d23 = __half22float2(*(__half2*)&dpk.y);
            float4 es = *(const float4*)&g_esrc[soff];
            float4 ed = *(const float4*)&g_edst[toff];
            float4 m;
            m.x = d01.x + bb.x + es.x + ed.x;
            m.y = d01.y + bb.y + es.y + ed.y;
            m.z = d23.x + bb.z + es.z + ed.z;
            m.w = d23.y + bb.w + es.w + ed.w;

            __half2 h0 = __floats2half2_rn(m.x, m.y);
            __half2 h1 = __floats2half2_rn(m.z, m.w);
            *(uint2*)(g_mh + (size_t)e*64 + tx*4) = make_uint2(h2bits(h0), h2bits(h1));

            ls[0] += m.x; lq[0] += m.x*m.x;
            ls[1] += m.y; lq[1] += m.y*m.y;
            ls[2] += m.z; lq[2] += m.z*m.z;
            ls[3] += m.w; lq[3] += m.w*m.w;

            float4 bh = *(const float4*)&g_Bh[soff];
            float sg0 = fsigmoid(m.x), sg1 = fsigmoid(m.y);
            float sg2 = fsigmoid(m.z), sg3 = fsigmoid(m.w);
            red_add_v4(&g_sums[toff], sg0, sg1, sg2, sg3);
            red_add_v4(&g_sumh[toff], bh.x*sg0, bh.y*sg1, bh.z*sg2, bh.w*sg3);
        }
    }

    // block-level BN stats reduction: feature d = tx*4 + comp, reduce over ty
    #pragma unroll
    for (int comp = 0; comp < 4; comp++) {
        __syncthreads();
        sred[tid] = ls[comp];
        __syncthreads();
        if (ty == 0) {
            float ssum = 0.f;
            #pragma unroll
            for (int j = 0; j < 16; j++) ssum += sred[j*16 + tx];
            atomicAdd(&g_stats[tx*4 + comp], ssum);
        }
        __syncthreads();
        sred[tid] = lq[comp];
        __syncthreads();
        if (ty == 0) {
            float ssum = 0.f;
            #pragma unroll
            for (int j = 0; j < 16; j++) ssum += sred[j*16 + tx];
            atomicAdd(&g_stats[64 + tx*4 + comp], ssum);
        }
    }
}

// ---------------- K3: node finalize: x_pre = xs + h, node-BN stats -----------
__global__ void __launch_bounds__(256) k_node_fin() {
    int tid = threadIdx.x;
    int d = tid & 63;
    int stride = gridDim.x * 256;
    float lsum = 0.f, lsq = 0.f;
    for (int i = blockIdx.x * 256 + tid; i < NN*DD; i += stride) {
        float xp = g_xs[i] + g_sumh[i] / (g_sums[i] + 1e-6f);
        g_xs[i] = xp;
        lsum += xp; lsq += xp*xp;
    }
    __shared__ float sred[256];
    sred[tid] = lsum;
    __syncthreads();
    if (tid < 64)
        atomicAdd(&g_stats[128 + d], sred[d] + sred[64+d] + sred[128+d] + sred[192+d]);
    __syncthreads();
    sred[tid] = lsq;
    __syncthreads();
    if (tid < 64)
        atomicAdd(&g_stats[192 + d], sred[d] + sred[64+d] + sred[128+d] + sred[192+d]);
}

// ---------------- K4: BN scale/shift ----------------------------------------
__global__ void k_bn(const float* __restrict__ gn, const float* __restrict__ btn,
                     const float* __restrict__ ge, const float* __restrict__ bte)
{
    int d = threadIdx.x;   // 64 threads
    float me = g_stats[d] * (1.f / EE);
    float ve = g_stats[64 + d] * (1.f / EE) - me * me;
    float se = ge[d] * rsqrtf(ve + 1e-5f);
    g_bn[128 + d] = se;
    g_bn[192 + d] = bte[d] - me * se;

    float mn = g_stats[128 + d] * (1.f / NN);
    float vn = g_stats[192 + d] * (1.f / NN) - mn * mn;
    float sn = gn[d] * rsqrtf(vn + 1e-5f);
    g_bn[d]      = sn;
    g_bn[64 + d] = btn[d] - mn * sn;
}

// ---------------- K5: node output -------------------------------------------
__global__ void __launch_bounds__(256) k_node_out(const float* __restrict__ nf,
                                                  float* __restrict__ out)
{
    int i4 = blockIdx.x * 256 + threadIdx.x;
    if (i4 >= NN*DD/4) return;
    int d4 = (i4 & 15) * 4;
    float4 sc = *(const float4*)&g_bn[d4];
    float4 sh = *(const float4*)&g_bn[64 + d4];
    float4 xp = *(const float4*)&g_xs[i4*4];
    float4 bs = *(const float4*)&nf[i4*4];
    float4 o;
    o.x = bs.x + fsilu(xp.x*sc.x + sh.x);
    o.y = bs.y + fsilu(xp.y*sc.y + sh.y);
    o.z = bs.z + fsilu(xp.z*sc.z + sh.z);
    o.w = bs.w + fsilu(xp.w*sc.w + sh.w);
    *(float4*)&out[i4*4] = o;
}

// ---------------- K6: edge output (fp16 m) -----------------------------------
__global__ void __launch_bounds__(256) k_edge_out(const float* __restrict__ ef,
                                                  float* __restrict__ out)
{
    int stride = gridDim.x * 256;
    for (int i4 = blockIdx.x * 256 + threadIdx.x; i4 < EE*DD/4; i4 += stride) {
        int d4 = (i4 & 15) * 4;
        float4 sc = *(const float4*)&g_bn[128 + d4];
        float4 sh = *(const float4*)&g_bn[192 + d4];
        uint2 pk = *(const uint2*)(g_mh + (size_t)i4*4);
        __half2 h0 = *(__half2*)&pk.x;
        __half2 h1 = *(__half2*)&pk.y;
        float2 m01 = __half22float2(h0);
        float2 m23 = __half22float2(h1);
        float4 bs = *(const float4*)&ef[i4*4];
        float4 o;
        o.x = bs.x + fsilu(m01.x*sc.x + sh.x);
        o.y = bs.y + fsilu(m01.y*sc.y + sh.y);
        o.z = bs.z + fsilu(m23.x*sc.z + sh.z);
        o.w = bs.w + fsilu(m23.y*sc.w + sh.w);
        *(float4*)&out[i4*4] = o;
    }
}

// ---------------- launcher ---------------------------------------------------
extern "C" void kernel_launch(void* const* d_in, const int* in_sizes, int n_in,
                              void* d_out, int out_size)
{
    const float* nf  = (const float*)d_in[0];
    const float* ef  = (const float*)d_in[1];
    const int*   src = (const int*)  d_in[2];
    const int*   dst = (const int*)  d_in[3];
    const float *Wsg = (const float*)d_in[4],  *bsg = (const float*)d_in[5];
    const float *Wdg = (const float*)d_in[6],  *bdg = (const float*)d_in[7];
    const float *Weg = (const float*)d_in[8],  *beg = (const float*)d_in[9];
    const float *Wsu = (const float*)d_in[10], *bsu = (const float*)d_in[11];
    const float *Wdu = (const float*)d_in[12], *bdu = (const float*)d_in[13];
    const float *gn  = (const float*)d_in[14], *btn = (const float*)d_in[15];
    const float *ge  = (const float*)d_in[16], *bte = (const float*)d_in[17];
    float* out = (float*)d_out;

    cudaFuncSetAttribute(k_node_gemm, cudaFuncAttributeMaxDynamicSharedMemorySize,
                         NG_TOTAL);
    cudaFuncSetAttribute(k_edge, cudaFuncAttributeMaxDynamicSharedMemorySize,
                         SM_EDGE_TOTAL);

    k_zero_a<<<1, 256>>>();                                           // launch 0
    k_node_gemm<<<391, 256, NG_TOTAL>>>(nf, Wsg, bsg, Wdg, bdg,
                                        Wdu, bdu, Wsu, bsu);          // launch 1
    k_zero_b<<<1, 256>>>();                                           // launch 2
    k_edge<<<2960, 256, SM_EDGE_TOTAL>>>(ef, src, dst, Weg, beg);     // launch 3 (profiled)
    k_node_fin<<<1024, 256>>>();                                      // launch 4
    k_bn<<<1, 64>>>(gn, btn, ge, bte);                                // launch 5
    k_node_out<<<3125, 256>>>(nf, out);                               // launch 6
    k_edge_out<<<8192, 256>>>(ef, out + NN*DD);                       // launch 7
}

// round 16
// speedup vs baseline: 2.1586x; 1.0022x over previous
#include <cuda_runtime.h>
#include <cuda_fp16.h>
#include <math.h>
#include <cstdint>

#define NN 50000
#define EE 800000
#define DD 64

typedef unsigned long long u64;

// ---------------- scratch (static device globals; no runtime allocation) ----
__device__ __align__(16) float g_esrc[NN*DD];
__device__ __align__(16) float g_edst[NN*DD];
__device__ __align__(16) float g_Bh[NN*DD];
__device__ __align__(16) float g_xs[NN*DD];      // xs, then x_pre in-place
__device__ __align__(16) __half g_mh[EE*DD];     // m stored fp16 (102.4 MB)
__device__ __align__(16) float g_sumh[NN*DD];
__device__ __align__(16) float g_sums[NN*DD];
// stats: [0..63] e_sum, [64..127] e_sumsq, [128..191] n_sum, [192..255] n_sumsq
__device__ __align__(16) float g_stats[256];

__device__ __forceinline__ float fsigmoid(float x) { return 1.f / (1.f + __expf(-x)); }
__device__ __forceinline__ float fsilu(float z)    { return z / (1.f + __expf(-z)); }
__device__ __forceinline__ unsigned h2bits(__half2 h) { return *(unsigned*)&h; }

// vectorized no-return fp32 reduction: 1 instruction, 16 bytes, 4 lanes
__device__ __forceinline__ void red_add_v4(float* addr, float a, float b, float c, float d) {
    asm volatile("red.global.add.v4.f32 [%0], {%1,%2,%3,%4};"
                 :: "l"(addr), "f"(a), "f"(b), "f"(c), "f"(d) : "memory");
}

// warp-level tensor-core mma (baseline PTX, valid on sm_103 non-'a' target)
__device__ __forceinline__ void mma_16816(float* c, uint32_t a0, uint32_t a1,
                                          uint32_t a2, uint32_t a3,
                                          uint32_t b0, uint32_t b1) {
    asm volatile(
        "mma.sync.aligned.m16n8k16.row.col.f32.f16.f16.f32 "
        "{%0,%1,%2,%3}, {%4,%5,%6,%7}, {%8,%9}, {%0,%1,%2,%3};"
        : "+f"(c[0]), "+f"(c[1]), "+f"(c[2]), "+f"(c[3])
        : "r"(a0), "r"(a1), "r"(a2), "r"(a3), "r"(b0), "r"(b1));
}

// k_edge smem byte offsets (dynamic smem, 48128 B total -> 4 blocks/SM)
#define SM_IDX  0         // 256 ints (1024 B)
#define SM_SRED 1024      // 256 floats (1024 B)
#define SM_W    2048      // 64 rows x 72 halves packed  (9216 B)
#define SM_A    11264     // 128 rows x 72 halves        (18432 B)
#define SM_D    29696     // 128 rows x 72 halves (fp16 D stage, 18432 B)
#define SM_EDGE_TOTAL 48128

// k_node_gemm smem byte offsets (90112 B -> 2 blocks/SM)
#define NG_W    0         // 4 matrices x 64 x 72 halves (36864 B)
#define NG_A    36864     // 128 x 72 halves             (18432 B)
#define NG_D    55296     // 128 x 68 floats             (34816 B)
#define NG_TOTAL 90112

// ---------------- K1: node GEMMs via mma.sync (e_src, e_dst, Bh, xs) --------
// 128 nodes/chunk, one fp16 A tile reused for 4 weight matrices. Epilogue adds
// bias, stores fp32; matrix 0's pass also zeroes g_sums/g_sumh. Block 0 zeroes
// g_stats (nothing reads it until k_edge's end-of-kernel atomics).
__global__ void __launch_bounds__(256, 2) k_node_gemm(
    const float* __restrict__ nf,
    const float* __restrict__ Wsg, const float* __restrict__ bsg,
    const float* __restrict__ Wdg, const float* __restrict__ bdg,
    const float* __restrict__ Wdu, const float* __restrict__ bdu,
    const float* __restrict__ Wsu, const float* __restrict__ bsu)
{
    extern __shared__ char smem[];
    __half* sW = (__half*)(smem + NG_W);
    __half* sA = (__half*)(smem + NG_A);
    float*  sD = (float*)(smem + NG_D);

    int tid = threadIdx.x;
    int wid = tid >> 5, lane = tid & 31;
    int tig = lane & 3, grp = lane >> 2;
    int tx = tid & 15, ty = tid >> 4;

    if (blockIdx.x == 0) g_stats[tid] = 0.f;

    // pack all 4 weight matrices (k_edge layout per matrix)
    #pragma unroll
    for (int jm = 0; jm < 4; jm++) {
        const float* Wp = (jm == 0) ? Wsg : (jm == 1) ? Wdg : (jm == 2) ? Wdu : Wsu;
        for (int i = tid; i < 4096; i += 256) {
            int k = i >> 6, n = i & 63;
            int s = k >> 4, r = k & 15;
            int q = (r & 7) >> 1, hi = r >> 3, lo = r & 1;
            sW[jm*4608 + n*72 + s*16 + q*4 + hi*2 + lo] = __float2half_rn(Wp[i]);
        }
    }
    float4 bb[4];
    bb[0] = *(const float4*)(bsg + tx*4);
    bb[1] = *(const float4*)(bdg + tx*4);
    bb[2] = *(const float4*)(bdu + tx*4);
    bb[3] = *(const float4*)(bsu + tx*4);

    int nchunk = (NN + 127) / 128;        // 391
    for (int c = blockIdx.x; c < nchunk; c += gridDim.x) {
        int base = c * 128;
        __syncthreads();                  // prev chunk's last epilogue done
        #pragma unroll
        for (int l = 0; l < 8; l++) {
            int idx = tid + l * 256;
            int r = idx >> 4, c4 = (idx & 15) * 4;
            int row = base + r;
            float4 v = make_float4(0.f, 0.f, 0.f, 0.f);
            if (row < NN) v = *(const float4*)(nf + row*64 + c4);
            __half2 h0 = __floats2half2_rn(v.x, v.y);
            __half2 h1 = __floats2half2_rn(v.z, v.w);
            *(uint2*)(sA + r*72 + c4) = make_uint2(h2bits(h0), h2bits(h1));
        }
        __syncthreads();

        #pragma unroll
        for (int jm = 0; jm < 4; jm++) {
            float acc[8][4];
            #pragma unroll
            for (int j = 0; j < 8; j++) {
                acc[j][0] = 0.f; acc[j][1] = 0.f; acc[j][2] = 0.f; acc[j][3] = 0.f;
            }
            const __half* arow  = sA + (wid*16 + grp)*72;
            const __half* wbase = sW + jm*4608;
            #pragma unroll
            for (int s = 0; s < 4; s++) {
                int k0 = s*16 + tig*2;
                uint32_t a0 = *(const uint32_t*)(arow + k0);
                uint32_t a1 = *(const uint32_t*)(arow + 8*72 + k0);
                uint32_t a2 = *(const uint32_t*)(arow + k0 + 8);
                uint32_t a3 = *(const uint32_t*)(arow + 8*72 + k0 + 8);
                #pragma unroll
                for (int j = 0; j < 8; j++) {
                    uint2 b = *(const uint2*)(wbase + (j*8 + grp)*72 + s*16 + tig*4);
                    mma_16816(acc[j], a0, a1, a2, a3, b.x, b.y);
                }
            }

            // stage D (fp32) to smem
            float* drow = sD + (wid*16 + grp)*68;
            #pragma unroll
            for (int j = 0; j < 8; j++) {
                *(float2*)(drow + j*8 + tig*2)        = make_float2(acc[j][0], acc[j][1]);
                *(float2*)(drow + 8*68 + j*8 + tig*2) = make_float2(acc[j][2], acc[j][3]);
            }
            __syncthreads();

            // epilogue: bias + store fp32
            float* outp = (jm == 0) ? g_esrc : (jm == 1) ? g_edst : (jm == 2) ? g_Bh : g_xs;
            #pragma unroll
            for (int r = 0; r < 8; r++) {
                int row = ty*8 + r;
                int nrow = base + row;
                if (nrow < NN) {
                    int off = nrow*64 + tx*4;
                    float4 d = *(const float4*)(sD + row*68 + tx*4);
                    d.x += bb[jm].x; d.y += bb[jm].y; d.z += bb[jm].z; d.w += bb[jm].w;
                    *(float4*)&outp[off] = d;
                    if (jm == 0) {
                        *(float4*)&g_sums[off] = make_float4(0.f, 0.f, 0.f, 0.f);
                        *(float4*)&g_sumh[off] = make_float4(0.f, 0.f, 0.f, 0.f);
                    }
                }
            }
            __syncthreads();              // protect sD before next jm's stage
        }
    }
}

// ---------------- K2: edge kernel — mma.sync f16 GEMM + fused epilogue ------
// (unchanged from R13/R15: 175.6 us, occ 48%)
__global__ void __launch_bounds__(256, 4) k_edge(
    const float* __restrict__ ef, const int* __restrict__ src, const int* __restrict__ dst,
    const float* __restrict__ Weg, const float* __restrict__ beg)
{
    extern __shared__ char smem[];
    int*    sidx = (int*)(smem + SM_IDX);
    float*  sred = (float*)(smem + SM_SRED);
    __half* sW   = (__half*)(smem + SM_W);
    __half* sA   = (__half*)(smem + SM_A);
    __half* sD   = (__half*)(smem + SM_D);

    int tid = threadIdx.x;
    int wid = tid >> 5, lane = tid & 31;
    int tig = lane & 3, grp = lane >> 2;
    int tx = tid & 15, ty = tid >> 4;

    // W fill: packed so B frag (b0,b1) = one 8-byte load.
    for (int i = tid; i < 4096; i += 256) {
        int k = i >> 6, n = i & 63;
        int s = k >> 4, r = k & 15;
        int q = (r & 7) >> 1, hi = r >> 3, lo = r & 1;
        sW[n*72 + s*16 + q*4 + hi*2 + lo] = __float2half_rn(Weg[i]);
    }
    float4 bb = *(const float4*)(beg + tx*4);

    float ls[4] = {0.f,0.f,0.f,0.f};
    float lq[4] = {0.f,0.f,0.f,0.f};

    int nchunk = EE / 128;    // 6250
    for (int c = blockIdx.x; c < nchunk; c += gridDim.x) {
        int base = c * 128;
        __syncthreads();      // prev epilogue done (sA/sidx reuse)
        #pragma unroll
        for (int l = 0; l < 8; l++) {
            int idx = tid + l * 256;             // float4 index 0..2047
            int r = idx >> 4, c4 = (idx & 15) * 4;
            float4 v = *(const float4*)(ef + (base + r)*64 + c4);
            __half2 h0 = __floats2half2_rn(v.x, v.y);
            __half2 h1 = __floats2half2_rn(v.z, v.w);
            *(uint2*)(sA + r*72 + c4) = make_uint2(h2bits(h0), h2bits(h1));
        }
        if (tid < 128) sidx[tid] = src[base + tid];
        else           sidx[tid] = dst[base + tid - 128];
        __syncthreads();

        float acc[8][4];
        #pragma unroll
        for (int j = 0; j < 8; j++) {
            acc[j][0] = 0.f; acc[j][1] = 0.f; acc[j][2] = 0.f; acc[j][3] = 0.f;
        }

        const __half* arow = sA + (wid*16 + grp)*72;
        #pragma unroll
        for (int s = 0; s < 4; s++) {
            int k0 = s*16 + tig*2;
            uint32_t a0 = *(const uint32_t*)(arow + k0);
            uint32_t a1 = *(const uint32_t*)(arow + 8*72 + k0);
            uint32_t a2 = *(const uint32_t*)(arow + k0 + 8);
            uint32_t a3 = *(const uint32_t*)(arow + 8*72 + k0 + 8);
            #pragma unroll
            for (int j = 0; j < 8; j++) {
                uint2 b = *(const uint2*)(sW + (j*8 + grp)*72 + s*16 + tig*4);
                mma_16816(acc[j], a0, a1, a2, a3, b.x, b.y);
            }
        }

        // stage D to smem as fp16
        __half* drow = sD + (wid*16 + grp)*72;
        #pragma unroll
        for (int j = 0; j < 8; j++) {
            *(uint32_t*)(drow + j*8 + tig*2)        = h2bits(__floats2half2_rn(acc[j][0], acc[j][1]));
            *(uint32_t*)(drow + 8*72 + j*8 + tig*2) = h2bits(__floats2half2_rn(acc[j][2], acc[j][3]));
        }
        __syncthreads();

        // epilogue (R7 mapping: ty -> 8 rows, tx -> col quad)
        #pragma unroll
        for (int r = 0; r < 8; r++) {
            int row = ty*8 + r;
            int e = base + row;
            int s = sidx[row], t = sidx[128 + row];
            const int soff = s*64 + tx*4;
            const int toff = t*64 + tx*4;
            uint2 dpk = *(const uint2*)(sD + row*72 + tx*4);
            float2 d01 = __half22float2(*(__half2*)&dpk.x);
            float2 d23 = __half22float2(*(__half2*)&dpk.y);
            float4 es = *(const float4*)&g_esrc[soff];
            float4 ed = *(const float4*)&g_edst[toff];
            float4 m;
            m.x = d01.x + bb.x + es.x + ed.x;
            m.y = d01.y + bb.y + es.y + ed.y;
            m.z = d23.x + bb.z + es.z + ed.z;
            m.w = d23.y + bb.w + es.w + ed.w;

            __half2 h0 = __floats2half2_rn(m.x, m.y);
            __half2 h1 = __floats2half2_rn(m.z, m.w);
            *(uint2*)(g_mh + (size_t)e*64 + tx*4) = make_uint2(h2bits(h0), h2bits(h1));

            ls[0] += m.x; lq[0] += m.x*m.x;
            ls[1] += m.y; lq[1] += m.y*m.y;
            ls[2] += m.z; lq[2] += m.z*m.z;
            ls[3] += m.w; lq[3] += m.w*m.w;

            float4 bh = *(const float4*)&g_Bh[soff];
            float sg0 = fsigmoid(m.x), sg1 = fsigmoid(m.y);
            float sg2 = fsigmoid(m.z), sg3 = fsigmoid(m.w);
            red_add_v4(&g_sums[toff], sg0, sg1, sg2, sg3);
            red_add_v4(&g_sumh[toff], bh.x*sg0, bh.y*sg1, bh.z*sg2, bh.w*sg3);
        }
    }

    // block-level BN stats reduction: feature d = tx*4 + comp, reduce over ty
    #pragma unroll
    for (int comp = 0; comp < 4; comp++) {
        __syncthreads();
        sred[tid] = ls[comp];
        __syncthreads();
        if (ty == 0) {
            float ssum = 0.f;
            #pragma unroll
            for (int j = 0; j < 16; j++) ssum += sred[j*16 + tx];
            atomicAdd(&g_stats[tx*4 + comp], ssum);
        }
        __syncthreads();
        sred[tid] = lq[comp];
        __syncthreads();
        if (ty == 0) {
            float ssum = 0.f;
            #pragma unroll
            for (int j = 0; j < 16; j++) ssum += sred[j*16 + tx];
            atomicAdd(&g_stats[64 + tx*4 + comp], ssum);
        }
    }
}

// ---------------- K3: node finalize: x_pre = xs + h, node-BN stats -----------
__global__ void __launch_bounds__(256) k_node_fin() {
    int tid = threadIdx.x;
    int d = tid & 63;
    int stride = gridDim.x * 256;
    float lsum = 0.f, lsq = 0.f;
    for (int i = blockIdx.x * 256 + tid; i < NN*DD; i += stride) {
        float xp = g_xs[i] + g_sumh[i] / (g_sums[i] + 1e-6f);
        g_xs[i] = xp;
        lsum += xp; lsq += xp*xp;
    }
    __shared__ float sred[256];
    sred[tid] = lsum;
    __syncthreads();
    if (tid < 64)
        atomicAdd(&g_stats[128 + d], sred[d] + sred[64+d] + sred[128+d] + sred[192+d]);
    __syncthreads();
    sred[tid] = lsq;
    __syncthreads();
    if (tid < 64)
        atomicAdd(&g_stats[192 + d], sred[d] + sred[64+d] + sred[128+d] + sred[192+d]);
}

// ---------------- K4: fused output (edge + node), BN params computed inline --
// Work units: [0, 6.4M) = edge octets (8 features), [6.4M, 7.2M) = node quads.
// Grid = 28125 blocks x 256 = 7.2M threads exactly, one unit per thread.
#define NEDGE8 (EE * 8)            // 6,400,000
#define NTOT   (NEDGE8 + NN*16)    // 7,200,000
__global__ void __launch_bounds__(256) k_output(
    const float* __restrict__ nf, const float* __restrict__ ef,
    const float* __restrict__ gn, const float* __restrict__ btn,
    const float* __restrict__ ge, const float* __restrict__ bte,
    float* __restrict__ out)
{
    __shared__ float sbn[256];   // [0:64) sc_n, [64:128) sh_n, [128:192) sc_e, [192:256) sh_e
    int tid = threadIdx.x;
    if (tid < 64) {
        float me = g_stats[tid] * (1.f / EE);
        float ve = g_stats[64 + tid] * (1.f / EE) - me * me;
        float se = ge[tid] * rsqrtf(ve + 1e-5f);
        sbn[128 + tid] = se;
        sbn[192 + tid] = bte[tid] - me * se;
        float mn = g_stats[128 + tid] * (1.f / NN);
        float vn = g_stats[192 + tid] * (1.f / NN) - mn * mn;
        float sn = gn[tid] * rsqrtf(vn + 1e-5f);
        sbn[tid]      = sn;
        sbn[64 + tid] = btn[tid] - mn * sn;
    }
    __syncthreads();

    int idx = blockIdx.x * 256 + tid;
    if (idx < NEDGE8) {
        // edge octet: 8 consecutive features
        int d8 = (idx & 7) * 8;
        size_t off = (size_t)idx * 8;
        uint4 pk = *(const uint4*)(g_mh + off);
        float2 m0 = __half22float2(*(__half2*)&pk.x);
        float2 m1 = __half22float2(*(__half2*)&pk.y);
        float2 m2 = __half22float2(*(__half2*)&pk.z);
        float2 m3 = __half22float2(*(__half2*)&pk.w);
        float4 sc0 = *(const float4*)&sbn[128 + d8];
        float4 sc1 = *(const float4*)&sbn[128 + d8 + 4];
        float4 sh0 = *(const float4*)&sbn[192 + d8];
        float4 sh1 = *(const float4*)&sbn[192 + d8 + 4];
        float4 e0 = *(const float4*)&ef[off];
        float4 e1 = *(const float4*)&ef[off + 4];
        float4 o0, o1;
        o0.x = e0.x + fsilu(m0.x*sc0.x + sh0.x);
        o0.y = e0.y + fsilu(m0.y*sc0.y + sh0.y);
        o0.z = e0.z + fsilu(m1.x*sc0.z + sh0.z);
        o0.w = e0.w + fsilu(m1.y*sc0.w + sh0.w);
        o1.x = e1.x + fsilu(m2.x*sc1.x + sh1.x);
        o1.y = e1.y + fsilu(m2.y*sc1.y + sh1.y);
        o1.z = e1.z + fsilu(m3.x*sc1.z + sh1.z);
        o1.w = e1.w + fsilu(m3.y*sc1.w + sh1.w);
        float* op = out + (size_t)NN*DD + off;
        *(float4*)op       = o0;
        *(float4*)(op + 4) = o1;
    } else {
        // node quad
        int i4 = idx - NEDGE8;           // [0, 800000)
        int d4 = (i4 & 15) * 4;
        float4 sc = *(const float4*)&sbn[d4];
        float4 sh = *(const float4*)&sbn[64 + d4];
        float4 xp = *(const float4*)&g_xs[i4*4];
        float4 bs = *(const float4*)&nf[i4*4];
        float4 o;
        o.x = bs.x + fsilu(xp.x*sc.x + sh.x);
        o.y = bs.y + fsilu(xp.y*sc.y + sh.y);
        o.z = bs.z + fsilu(xp.z*sc.z + sh.z);
        o.w = bs.w + fsilu(xp.w*sc.w + sh.w);
        *(float4*)&out[i4*4] = o;
    }
}

// ---------------- launcher ---------------------------------------------------
extern "C" void kernel_launch(void* const* d_in, const int* in_sizes, int n_in,
                              void* d_out, int out_size)
{
    const float* nf  = (const float*)d_in[0];
    const float* ef  = (const float*)d_in[1];
    const int*   src = (const int*)  d_in[2];
    const int*   dst = (const int*)  d_in[3];
    const float *Wsg = (const float*)d_in[4],  *bsg = (const float*)d_in[5];
    const float *Wdg = (const float*)d_in[6],  *bdg = (const float*)d_in[7];
    const float *Weg = (const float*)d_in[8],  *beg = (const float*)d_in[9];
    const float *Wsu = (const float*)d_in[10], *bsu = (const float*)d_in[11];
    const float *Wdu = (const float*)d_in[12], *bdu = (const float*)d_in[13];
    const float *gn  = (const float*)d_in[14], *btn = (const float*)d_in[15];
    const float *ge  = (const float*)d_in[16], *bte = (const float*)d_in[17];
    float* out = (float*)d_out;

    cudaFuncSetAttribute(k_node_gemm, cudaFuncAttributeMaxDynamicSharedMemorySize,
                         NG_TOTAL);
    cudaFuncSetAttribute(k_edge, cudaFuncAttributeMaxDynamicSharedMemorySize,
                         SM_EDGE_TOTAL);

    k_node_gemm<<<391, 256, NG_TOTAL>>>(nf, Wsg, bsg, Wdg, bdg,
                                        Wdu, bdu, Wsu, bsu);          // launch 0
    k_edge<<<2960, 256, SM_EDGE_TOTAL>>>(ef, src, dst, Weg, beg);     // launch 1
    k_node_fin<<<1024, 256>>>();                                      // launch 2
    k_output<<<28125, 256>>>(nf, ef, gn, btn, ge, bte, out);          // launch 3
}